// round 2
// baseline (speedup 1.0000x reference)
#include <cuda_runtime.h>
#include <math.h>

#define SS 2048
#define DD 1024
#define HH 8

// Scratch (allocation-free rule: __device__ globals)
__device__ float g_hidden[SS * DD];                       // 8 MB
__device__ float g_rel[SS * DD];                          // 8 MB
__device__ float g_Q[HH * SS * DD];                       // 64 MB
__device__ float g_logits[(size_t)HH * SS * SS];          // 128 MB
__device__ float g_ctx[(size_t)SS * HH * DD];             // 64 MB  ([S, H*D] layout)

// ---------------------------------------------------------------------------
// relation encoder stage 1: hidden = relu(relations @ re_w1 + b1), K=4
// ---------------------------------------------------------------------------
__global__ void relenc1_kernel(const float* __restrict__ rel4,
                               const float* __restrict__ w1,
                               const float* __restrict__ b1,
                               float* __restrict__ hid) {
    int idx = blockIdx.x * 256 + threadIdx.x;     // over S*D
    int s = idx >> 10;
    int j = idx & 1023;
    float acc = b1[j];
#pragma unroll
    for (int k = 0; k < 4; k++)
        acc += rel4[s * 4 + k] * w1[k * 1024 + j];
    hid[idx] = fmaxf(acc, 0.0f);
}

// ---------------------------------------------------------------------------
// Generic tiled SGEMM: C[M,N] = A[M,K] @ B + (bias)
//   BT=false : B is [K,N] row-major (NN)
//   BT=true  : B is [N,K] row-major (NT, i.e. C = A @ B^T)
// permHead >= 0 : output row r is stored at row (r&7)*SS + permHead*256 + (r>>3)
//   (folds the torch .view(B,S,H,-1) buffer reinterpretation into the store)
// ---------------------------------------------------------------------------
template <bool BT>
__global__ __launch_bounds__(256, 2)
void sgemm_kernel(const float* __restrict__ A, const float* __restrict__ B,
                  const float* __restrict__ bias, float* __restrict__ C,
                  int M, int N, int K, int lda, int ldb, int ldc, int permHead) {
    __shared__ float As[16][128];
    __shared__ float Bs[16][128];

    const int tid = threadIdx.x;
    const int tx = tid & 15;          // 0..15  -> N micro
    const int ty = tid >> 4;          // 0..15  -> M micro
    const int m0 = blockIdx.y * 128;
    const int n0 = blockIdx.x * 128;

    float acc[8][8];
#pragma unroll
    for (int i = 0; i < 8; i++)
#pragma unroll
        for (int j = 0; j < 8; j++) acc[i][j] = 0.0f;

    for (int k0 = 0; k0 < K; k0 += 16) {
        // ---- load A tile [128 rows x 16 k] (store transposed into As[k][m])
#pragma unroll
        for (int i = 0; i < 2; i++) {
            int flat = (tid + i * 256) * 4;       // 0..2044
            int r = flat >> 4;                    // row within tile
            int c = flat & 15;                    // k within tile (mult of 4)
            float4 v = *(const float4*)&A[(size_t)(m0 + r) * lda + k0 + c];
            As[c + 0][r] = v.x;
            As[c + 1][r] = v.y;
            As[c + 2][r] = v.z;
            As[c + 3][r] = v.w;
        }
        // ---- load B tile
        if (!BT) {
            // B is [K,N]: tile rows k0..k0+15, cols n0..n0+127
#pragma unroll
            for (int i = 0; i < 2; i++) {
                int flat = (tid + i * 256) * 4;
                int r = flat >> 7;                // k within tile
                int c = flat & 127;               // n within tile (mult of 4)
                *(float4*)&Bs[r][c] =
                    *(const float4*)&B[(size_t)(k0 + r) * ldb + n0 + c];
            }
        } else {
            // B is [N,K]: tile rows n0..n0+127, cols k0..k0+15 (store transposed)
#pragma unroll
            for (int i = 0; i < 2; i++) {
                int flat = (tid + i * 256) * 4;
                int r = flat >> 4;                // n within tile
                int c = flat & 15;                // k within tile
                float4 v = *(const float4*)&B[(size_t)(n0 + r) * ldb + k0 + c];
                Bs[c + 0][r] = v.x;
                Bs[c + 1][r] = v.y;
                Bs[c + 2][r] = v.z;
                Bs[c + 3][r] = v.w;
            }
        }
        __syncthreads();

#pragma unroll
        for (int kk = 0; kk < 16; kk++) {
            float a[8], b[8];
            *(float4*)&a[0] = *(const float4*)&As[kk][ty * 8 + 0];
            *(float4*)&a[4] = *(const float4*)&As[kk][ty * 8 + 4];
            *(float4*)&b[0] = *(const float4*)&Bs[kk][tx * 8 + 0];
            *(float4*)&b[4] = *(const float4*)&Bs[kk][tx * 8 + 4];
#pragma unroll
            for (int i = 0; i < 8; i++)
#pragma unroll
                for (int j = 0; j < 8; j++) acc[i][j] += a[i] * b[j];
        }
        __syncthreads();
    }

    // ---- epilogue
#pragma unroll
    for (int i = 0; i < 8; i++) {
        int r = m0 + ty * 8 + i;
        int crow = (permHead >= 0)
                       ? ((r & 7) * SS + permHead * 256 + (r >> 3))
                       : r;
        float* crowp = C + (size_t)crow * ldc + n0 + tx * 8;
        if (bias) {
            const float* bp = bias + n0 + tx * 8;
#pragma unroll
            for (int j = 0; j < 8; j++) crowp[j] = acc[i][j] + bp[j];
        } else {
#pragma unroll
            for (int j = 0; j < 8; j++) crowp[j] = acc[i][j];
        }
    }
}

// ---------------------------------------------------------------------------
// Row softmax, in place. grid = nrows, block = 256
// ---------------------------------------------------------------------------
__global__ void softmax_kernel(float* __restrict__ L, int ncols) {
    float* p = L + (size_t)blockIdx.x * ncols;
    const int tid = threadIdx.x;
    __shared__ float red[256];

    float m = -INFINITY;
    for (int c = tid; c < ncols; c += 256) m = fmaxf(m, p[c]);
    red[tid] = m;
    __syncthreads();
    for (int s = 128; s > 0; s >>= 1) {
        if (tid < s) red[tid] = fmaxf(red[tid], red[tid + s]);
        __syncthreads();
    }
    m = red[0];
    __syncthreads();

    float sum = 0.0f;
    for (int c = tid; c < ncols; c += 256) {
        float e = __expf(p[c] - m);
        p[c] = e;
        sum += e;
    }
    red[tid] = sum;
    __syncthreads();
    for (int s = 128; s > 0; s >>= 1) {
        if (tid < s) red[tid] += red[tid + s];
        __syncthreads();
    }
    float inv = 1.0f / red[0];
    for (int c = tid; c < ncols; c += 256) p[c] *= inv;
}

// ---------------------------------------------------------------------------
extern "C" void kernel_launch(void* const* d_in, const int* in_sizes, int n_in,
                              void* d_out, int out_size) {
    const float* x         = (const float*)d_in[0];  // [S, D]
    const float* relations = (const float*)d_in[1];  // [S, 4]
    const float* re_w1     = (const float*)d_in[2];  // [4, D]
    const float* re_b1     = (const float*)d_in[3];  // [D]
    const float* re_w2     = (const float*)d_in[4];  // [D, D]
    const float* re_b2     = (const float*)d_in[5];  // [D]
    const float* attn_w    = (const float*)d_in[6];  // [H, D, D]
    const float* out_w     = (const float*)d_in[7];  // [H*D, D]
    const float* out_b     = (const float*)d_in[8];  // [D]
    float* out = (float*)d_out;                      // [S, D]

    float *hid, *rel, *Q, *Lg, *ctx;
    cudaGetSymbolAddress((void**)&hid, g_hidden);
    cudaGetSymbolAddress((void**)&rel, g_rel);
    cudaGetSymbolAddress((void**)&Q, g_Q);
    cudaGetSymbolAddress((void**)&Lg, g_logits);
    cudaGetSymbolAddress((void**)&ctx, g_ctx);

    // 1. hidden = relu(relations @ re_w1 + b1)
    relenc1_kernel<<<(SS * DD) / 256, 256>>>(relations, re_w1, re_b1, hid);

    // 2. rel = hidden @ re_w2 + b2            [2048,1024]x[1024,1024]
    sgemm_kernel<false><<<dim3(DD / 128, SS / 128), 256>>>(
        hid, re_w2, re_b2, rel, SS, DD, DD, DD, DD, DD, -1);

    // 3. per-head Q = x @ attn_w[h], stored with the .view permutation
    for (int h = 0; h < HH; h++) {
        sgemm_kernel<false><<<dim3(DD / 128, SS / 128), 256>>>(
            x, attn_w + (size_t)h * DD * DD, nullptr, Q,
            SS, DD, DD, DD, DD, DD, h);
    }

    // 4. logits[h2] = rel @ Q[h2]^T           [2048,1024]x[1024,2048]
    for (int h2 = 0; h2 < HH; h2++) {
        sgemm_kernel<true><<<dim3(SS / 128, SS / 128), 256>>>(
            rel, Q + (size_t)h2 * SS * DD, nullptr,
            Lg + (size_t)h2 * SS * SS,
            SS, SS, DD, DD, DD, SS, -1);
    }

    // 5. softmax over last dim, all heads at once (16384 rows x 2048)
    softmax_kernel<<<HH * SS, 256>>>(Lg, SS);

    // 6. context[h2] = attn[h2] @ x, stored transposed into [S, H*D]
    for (int h2 = 0; h2 < HH; h2++) {
        sgemm_kernel<false><<<dim3(DD / 128, SS / 128), 256>>>(
            Lg + (size_t)h2 * SS * SS, x, nullptr,
            ctx + (size_t)h2 * DD,
            SS, DD, SS, SS, DD, HH * DD, -1);
    }

    // 7. out = ctx @ out_w + out_b            [2048,8192]x[8192,1024]
    sgemm_kernel<false><<<dim3(DD / 128, SS / 128), 256>>>(
        ctx, out_w, out_b, out, SS, DD, HH * DD, HH * DD, DD, DD, -1);
}

// round 7
// speedup vs baseline: 1.5317x; 1.5317x over previous
#include <cuda_runtime.h>
#include <cstdint>
#include <math.h>

#define SS 2048
#define DD 1024
#define HH 8

// ---------------- scratch (__device__ globals; allocation-free rule) -------
__device__ float g_hid_hi[SS * DD];
__device__ float g_hid_lo[SS * DD];
__device__ float g_w2t_hi[DD * DD];
__device__ float g_w2t_lo[DD * DD];
__device__ float g_awt_hi[HH * DD * DD];
__device__ float g_awt_lo[HH * DD * DD];
__device__ float g_x_hi[SS * DD];
__device__ float g_x_lo[SS * DD];
__device__ float g_xt[DD * SS];
__device__ float g_owt[DD * HH * DD];
__device__ float g_rel_hi[SS * DD];
__device__ float g_rel_lo[SS * DD];
__device__ float g_Q_hi[HH * SS * DD];
__device__ float g_Q_lo[HH * SS * DD];
__device__ float g_logits[(size_t)HH * SS * SS];
__device__ float g_ctx[(size_t)SS * HH * DD];

// ---------------- helpers ---------------------------------------------------
__device__ __forceinline__ float tf32_rna(float x) {
    uint32_t u;
    asm("cvt.rna.tf32.f32 %0, %1;" : "=r"(u) : "f"(x));
    return __uint_as_float(u);
}

__device__ __forceinline__ void mma8(float* d, uint32_t a0, uint32_t a1,
                                     uint32_t a2, uint32_t a3, uint32_t b0,
                                     uint32_t b1) {
    asm volatile(
        "mma.sync.aligned.m16n8k8.row.col.f32.tf32.tf32.f32 "
        "{%0,%1,%2,%3},{%4,%5,%6,%7},{%8,%9},{%0,%1,%2,%3};"
        : "+f"(d[0]), "+f"(d[1]), "+f"(d[2]), "+f"(d[3])
        : "r"(a0), "r"(a1), "r"(a2), "r"(a3), "r"(b0), "r"(b1));
}

#define LDT 36   // padded smem row stride (floats); 144B keeps 16B alignment
#define TILE_FLOATS (128 * LDT)

// gmem [128 rows x 32 k] -> smem with k-permutation p(kk) = (kk%4)*8 + kk/4
__device__ __forceinline__ void load_tile(float* dst, const float* src, int ld,
                                          int tid) {
#pragma unroll
    for (int it = 0; it < 4; it++) {
        int idx = tid + it * 256;          // 0..1023
        int r = idx >> 3;
        int t = idx & 7;                   // float4 group: kk = 4t..4t+3
        float4 v = *(const float4*)(src + (size_t)r * ld + t * 4);
        float* d = dst + r * LDT + t;
        d[0] = v.x;          // p = 0*8 + t
        d[8] = v.y;          // p = 1*8 + t
        d[16] = v.z;
        d[24] = v.w;
    }
}

// one (A-tile x B-tile) accumulation pass over a 32-k chunk
__device__ __forceinline__ void gemm_pass(const float* As, const float* Bs,
                                          float acc[4][4][4], int wm, int wn,
                                          int g, int c) {
#pragma unroll
    for (int sp = 0; sp < 2; sp++) {       // pairs of k-steps
        float4 a[4][2], b[4];
#pragma unroll
        for (int mt = 0; mt < 4; mt++) {
            int r0 = wm + mt * 16 + g;
            a[mt][0] = *(const float4*)&As[r0 * LDT + c * 8 + sp * 4];
            a[mt][1] = *(const float4*)&As[(r0 + 8) * LDT + c * 8 + sp * 4];
        }
#pragma unroll
        for (int nt = 0; nt < 4; nt++) {
            int nn = wn + nt * 8 + g;
            b[nt] = *(const float4*)&Bs[nn * LDT + c * 8 + sp * 4];
        }
#pragma unroll
        for (int s = 0; s < 2; s++) {
#pragma unroll
            for (int mt = 0; mt < 4; mt++) {
                uint32_t a0 = __float_as_uint(s ? a[mt][0].z : a[mt][0].x);
                uint32_t a2 = __float_as_uint(s ? a[mt][0].w : a[mt][0].y);
                uint32_t a1 = __float_as_uint(s ? a[mt][1].z : a[mt][1].x);
                uint32_t a3 = __float_as_uint(s ? a[mt][1].w : a[mt][1].y);
#pragma unroll
                for (int nt = 0; nt < 4; nt++) {
                    uint32_t b0 = __float_as_uint(s ? b[nt].z : b[nt].x);
                    uint32_t b1 = __float_as_uint(s ? b[nt].w : b[nt].y);
                    mma8(acc[mt][nt], a0, a1, a2, a3, b0, b1);
                }
            }
        }
    }
}

// ---------------------------------------------------------------------------
// mma.sync tf32 NT GEMM: C[M,N] = A[M,K] @ B[N,K]^T (+bias)
// SPLIT: 3-product hi/lo accumulation (fp32-accurate)
// Clo != null : epilogue writes tf32 hi/lo pair
// perm != 0   : output row r -> (r&7)*SS + z*256 + (r>>3)  (torch .view fold)
// rndC != 0   : round stored C values to tf32 (rna)
// ---------------------------------------------------------------------------
template <bool SPLIT>
__global__ void __launch_bounds__(256, 2)
mm_gemm(const float* __restrict__ A0, const float* __restrict__ A1,
        const float* __restrict__ B0, const float* __restrict__ B1,
        const float* __restrict__ bias,
        float* __restrict__ C, float* __restrict__ Clo,
        int M, int N, int K, int lda, int ldb, int ldc,
        long aZ, long bZ, long cZ, int perm, int rndC) {
    extern __shared__ float smf[];
    float* Ahs = smf;
    float* Bhs = smf + TILE_FLOATS;
    float* Als = smf + 2 * TILE_FLOATS;
    float* Bls = smf + 3 * TILE_FLOATS;

    const int tid = threadIdx.x;
    const int warp = tid >> 5, lane = tid & 31;
    const int g = lane >> 2, c = lane & 3;
    const int m0 = blockIdx.y * 128, n0 = blockIdx.x * 128;
    const int z = blockIdx.z;
    const int wm = (warp >> 2) * 64;
    const int wn = (warp & 3) * 32;

    const float* Ag = A0 + (size_t)z * aZ + (size_t)m0 * lda;
    const float* Bg = B0 + (size_t)z * bZ + (size_t)n0 * ldb;
    const float* Ag1 = SPLIT ? A1 + (size_t)z * aZ + (size_t)m0 * lda : nullptr;
    const float* Bg1 = SPLIT ? B1 + (size_t)z * bZ + (size_t)n0 * ldb : nullptr;

    float acc[4][4][4];
#pragma unroll
    for (int i = 0; i < 4; i++)
#pragma unroll
        for (int j = 0; j < 4; j++)
#pragma unroll
            for (int k = 0; k < 4; k++) acc[i][j][k] = 0.0f;

    for (int kc = 0; kc < K; kc += 32) {
        load_tile(Ahs, Ag + kc, lda, tid);
        load_tile(Bhs, Bg + kc, ldb, tid);
        if (SPLIT) {
            load_tile(Als, Ag1 + kc, lda, tid);
            load_tile(Bls, Bg1 + kc, ldb, tid);
        }
        __syncthreads();

        gemm_pass(Ahs, Bhs, acc, wm, wn, g, c);
        if (SPLIT) {
            gemm_pass(Ahs, Bls, acc, wm, wn, g, c);
            gemm_pass(Als, Bhs, acc, wm, wn, g, c);
        }
        __syncthreads();
    }

    // epilogue
    float* Cb = C + (size_t)z * cZ;
    float* Lb = Clo ? Clo + (size_t)z * cZ : nullptr;
#pragma unroll
    for (int mt = 0; mt < 4; mt++) {
#pragma unroll
        for (int half = 0; half < 2; half++) {
            int row = m0 + wm + mt * 16 + g + half * 8;
            long crow = perm ? ((long)(row & 7) * SS + (long)z * 256 + (row >> 3))
                             : (long)row;
#pragma unroll
            for (int nt = 0; nt < 4; nt++) {
                int col = n0 + wn + nt * 8 + c * 2;
                float v0 = acc[mt][nt][half * 2 + 0];
                float v1 = acc[mt][nt][half * 2 + 1];
                if (bias) {
                    v0 += bias[col];
                    v1 += bias[col + 1];
                }
                if (Lb) {
                    float h0 = tf32_rna(v0), h1 = tf32_rna(v1);
                    float l0 = tf32_rna(v0 - h0), l1 = tf32_rna(v1 - h1);
                    *(float2*)&Cb[crow * ldc + col] = make_float2(h0, h1);
                    *(float2*)&Lb[crow * ldc + col] = make_float2(l0, l1);
                } else {
                    if (rndC) {
                        v0 = tf32_rna(v0);
                        v1 = tf32_rna(v1);
                    }
                    *(float2*)&Cb[crow * ldc + col] = make_float2(v0, v1);
                }
            }
        }
    }
}

// ---------------- prep kernels ---------------------------------------------
__global__ void relenc1_split(const float* __restrict__ rel4,
                              const float* __restrict__ w1,
                              const float* __restrict__ b1,
                              float* __restrict__ hi, float* __restrict__ lo) {
    int idx = blockIdx.x * 256 + threadIdx.x;
    int s = idx >> 10, j = idx & 1023;
    float acc = b1[j];
#pragma unroll
    for (int k = 0; k < 4; k++) acc = fmaf(rel4[s * 4 + k], w1[k * 1024 + j], acc);
    acc = fmaxf(acc, 0.0f);
    float h = tf32_rna(acc);
    hi[idx] = h;
    lo[idx] = tf32_rna(acc - h);
}

__global__ void split_ew(const float* __restrict__ in, float* __restrict__ hi,
                         float* __restrict__ lo) {
    int i = blockIdx.x * 256 + threadIdx.x;
    float v = in[i];
    float h = tf32_rna(v);
    hi[i] = h;
    lo[i] = tf32_rna(v - h);
}

// out[c][r] = rna(in[r][c]) (+ lo part if SPLIT). block (32,8), grid (C/32, R/32, Z)
template <bool SPLIT>
__global__ void transpose_k(const float* __restrict__ in, float* __restrict__ ohi,
                            float* __restrict__ olo, int R, int C) {
    __shared__ float t[32][33];
    size_t zo = (size_t)blockIdx.z * R * C;
    int r0 = blockIdx.y * 32, c0 = blockIdx.x * 32;
#pragma unroll
    for (int i = 0; i < 32; i += 8)
        t[threadIdx.y + i][threadIdx.x] =
            in[zo + (size_t)(r0 + threadIdx.y + i) * C + c0 + threadIdx.x];
    __syncthreads();
#pragma unroll
    for (int i = 0; i < 32; i += 8) {
        float v = t[threadIdx.x][threadIdx.y + i];
        size_t o = zo + (size_t)(c0 + threadIdx.y + i) * R + r0 + threadIdx.x;
        if (SPLIT) {
            float h = tf32_rna(v);
            ohi[o] = h;
            olo[o] = tf32_rna(v - h);
        } else {
            ohi[o] = tf32_rna(v);
        }
    }
}

// ---------------- softmax (writes tf32-rounded probs) -----------------------
__global__ void softmax_kernel(float* __restrict__ L, int ncols) {
    float* p = L + (size_t)blockIdx.x * ncols;
    const int tid = threadIdx.x;
    __shared__ float red[256];

    float m = -INFINITY;
    for (int c = tid; c < ncols; c += 256) m = fmaxf(m, p[c]);
    red[tid] = m;
    __syncthreads();
    for (int s = 128; s > 0; s >>= 1) {
        if (tid < s) red[tid] = fmaxf(red[tid], red[tid + s]);
        __syncthreads();
    }
    m = red[0];
    __syncthreads();

    float sum = 0.0f;
    for (int c = tid; c < ncols; c += 256) {
        float e = __expf(p[c] - m);
        p[c] = e;
        sum += e;
    }
    red[tid] = sum;
    __syncthreads();
    for (int s = 128; s > 0; s >>= 1) {
        if (tid < s) red[tid] += red[tid + s];
        __syncthreads();
    }
    float inv = 1.0f / red[0];
    for (int c = tid; c < ncols; c += 256) p[c] = tf32_rna(p[c] * inv);
}

// ---------------------------------------------------------------------------
extern "C" void kernel_launch(void* const* d_in, const int* in_sizes, int n_in,
                              void* d_out, int out_size) {
    const float* x         = (const float*)d_in[0];  // [S, D]
    const float* relations = (const float*)d_in[1];  // [S, 4]
    const float* re_w1     = (const float*)d_in[2];  // [4, D]
    const float* re_b1     = (const float*)d_in[3];  // [D]
    const float* re_w2     = (const float*)d_in[4];  // [D, D]
    const float* re_b2     = (const float*)d_in[5];  // [D]
    const float* attn_w    = (const float*)d_in[6];  // [H, D, D]
    const float* out_w     = (const float*)d_in[7];  // [H*D, D]
    const float* out_b     = (const float*)d_in[8];  // [D]
    float* out = (float*)d_out;                      // [S, D]

    float *hid_hi, *hid_lo, *w2t_hi, *w2t_lo, *awt_hi, *awt_lo;
    float *x_hi, *x_lo, *xt, *owt, *rel_hi, *rel_lo, *Q_hi, *Q_lo, *Lg, *ctx;
    cudaGetSymbolAddress((void**)&hid_hi, g_hid_hi);
    cudaGetSymbolAddress((void**)&hid_lo, g_hid_lo);
    cudaGetSymbolAddress((void**)&w2t_hi, g_w2t_hi);
    cudaGetSymbolAddress((void**)&w2t_lo, g_w2t_lo);
    cudaGetSymbolAddress((void**)&awt_hi, g_awt_hi);
    cudaGetSymbolAddress((void**)&awt_lo, g_awt_lo);
    cudaGetSymbolAddress((void**)&x_hi, g_x_hi);
    cudaGetSymbolAddress((void**)&x_lo, g_x_lo);
    cudaGetSymbolAddress((void**)&xt, g_xt);
    cudaGetSymbolAddress((void**)&owt, g_owt);
    cudaGetSymbolAddress((void**)&rel_hi, g_rel_hi);
    cudaGetSymbolAddress((void**)&rel_lo, g_rel_lo);
    cudaGetSymbolAddress((void**)&Q_hi, g_Q_hi);
    cudaGetSymbolAddress((void**)&Q_lo, g_Q_lo);
    cudaGetSymbolAddress((void**)&Lg, g_logits);
    cudaGetSymbolAddress((void**)&ctx, g_ctx);

    const int SM_SPLIT = 4 * TILE_FLOATS * 4;   // 73728 B
    const int SM_PLAIN = 2 * TILE_FLOATS * 4;   // 36864 B
    cudaFuncSetAttribute(mm_gemm<true>, cudaFuncAttributeMaxDynamicSharedMemorySize,
                         SM_SPLIT);
    cudaFuncSetAttribute(mm_gemm<false>, cudaFuncAttributeMaxDynamicSharedMemorySize,
                         SM_PLAIN);

    // ---- prep
    relenc1_split<<<(SS * DD) / 256, 256>>>(relations, re_w1, re_b1, hid_hi, hid_lo);
    transpose_k<true><<<dim3(32, 32, 1), dim3(32, 8)>>>(re_w2, w2t_hi, w2t_lo,
                                                        1024, 1024);
    transpose_k<true><<<dim3(32, 32, 8), dim3(32, 8)>>>(attn_w, awt_hi, awt_lo,
                                                        1024, 1024);
    split_ew<<<(SS * DD) / 256, 256>>>(x, x_hi, x_lo);
    transpose_k<false><<<dim3(32, 64, 1), dim3(32, 8)>>>(x, xt, nullptr, 2048, 1024);
    transpose_k<false><<<dim3(32, 256, 1), dim3(32, 8)>>>(out_w, owt, nullptr,
                                                          8192, 1024);

    // ---- stage 2: rel = hid @ re_w2 + b2, split output
    mm_gemm<true><<<dim3(8, 16, 1), 256, SM_SPLIT>>>(
        hid_hi, hid_lo, w2t_hi, w2t_lo, re_b2, rel_hi, rel_lo,
        SS, DD, DD, DD, DD, DD, 0, 0, 0, 0, 0);

    // ---- stage 3: Q[h] = x @ attn_w[h], perm-store, split output (z = head)
    mm_gemm<true><<<dim3(8, 16, 8), 256, SM_SPLIT>>>(
        x_hi, x_lo, awt_hi, awt_lo, nullptr, Q_hi, Q_lo,
        SS, DD, DD, DD, DD, DD, 0, (long)DD * DD, 0, 1, 0);

    // ---- stage 4: logits[h2] = rel @ Q[h2]^T  (z = h2)
    mm_gemm<true><<<dim3(16, 16, 8), 256, SM_SPLIT>>>(
        rel_hi, rel_lo, Q_hi, Q_lo, nullptr, Lg, nullptr,
        SS, SS, DD, DD, DD, SS, 0, (long)SS * DD, (long)SS * SS, 0, 0);

    // ---- stage 5: softmax (rounds probs to tf32)
    softmax_kernel<<<HH * SS, 256>>>(Lg, SS);

    // ---- stage 6: ctx[:, h*D:(h+1)*D] = attn[h] @ x  (B = x^T, z = h)
    mm_gemm<false><<<dim3(8, 16, 8), 256, SM_PLAIN>>>(
        Lg, nullptr, xt, nullptr, nullptr, ctx, nullptr,
        SS, DD, SS, SS, SS, HH * DD, (long)SS * SS, 0, (long)DD, 0, 1);

    // ---- stage 7: out = ctx @ out_w + b
    mm_gemm<false><<<dim3(8, 16, 1), 256, SM_PLAIN>>>(
        ctx, nullptr, owt, nullptr, out_b, out, nullptr,
        SS, DD, HH * DD, HH * DD, HH * DD, DD, 0, 0, 0, 0, 0);
}

// round 11
// speedup vs baseline: 2.5114x; 1.6396x over previous
#include <cuda_runtime.h>
#include <cstdint>
#include <math.h>

#define SS 2048
#define DD 1024
#define HH 8

// ---------------- scratch (__device__ globals; allocation-free rule) -------
__device__ float g_hid_hi[SS * DD];
__device__ float g_hid_lo[SS * DD];
__device__ float g_w2t_hi[DD * DD];
__device__ float g_w2t_lo[DD * DD];
__device__ float g_awt_hi[HH * DD * DD];
__device__ float g_awt_lo[HH * DD * DD];
__device__ float g_x_hi[SS * DD];
__device__ float g_x_lo[SS * DD];
__device__ float g_xt[DD * SS];
__device__ float g_owt[DD * HH * DD];
__device__ float g_rel_hi[SS * DD];
__device__ float g_rel_lo[SS * DD];
__device__ float g_Q_hi[HH * SS * DD];
__device__ float g_Q_lo[HH * SS * DD];
__device__ float g_logits[(size_t)HH * SS * SS];
__device__ float g_ctx[(size_t)SS * HH * DD];

// ---------------- helpers ---------------------------------------------------
__device__ __forceinline__ float tf32_rna(float x) {
    uint32_t u;
    asm("cvt.rna.tf32.f32 %0, %1;" : "=r"(u) : "f"(x));
    return __uint_as_float(u);
}
__device__ __forceinline__ uint32_t smem_u32(const void* p) {
    uint32_t a;
    asm("{ .reg .u64 t; cvta.to.shared.u64 t, %1; cvt.u32.u64 %0, t; }"
        : "=r"(a) : "l"(p));
    return a;
}
// k-permutation within 32-groups: element k stored at (k%4)*8 + k/4
__device__ __forceinline__ int permk(int k) {
    int q = k & 31;
    return (k & ~31) | ((q & 3) << 3) | (q >> 2);
}
__device__ __forceinline__ void mma8(float* d, uint32_t a0, uint32_t a1,
                                     uint32_t a2, uint32_t a3, uint32_t b0,
                                     uint32_t b1) {
    asm volatile(
        "mma.sync.aligned.m16n8k8.row.col.f32.tf32.tf32.f32 "
        "{%0,%1,%2,%3},{%4,%5,%6,%7},{%8,%9},{%0,%1,%2,%3};"
        : "+f"(d[0]), "+f"(d[1]), "+f"(d[2]), "+f"(d[3])
        : "r"(a0), "r"(a1), "r"(a2), "r"(a3), "r"(b0), "r"(b1));
}

#define TFL (128 * 32)   // floats per 128x32 tile (16 KB)

// async-copy one 128x32 tile; gmem is k-pre-permuted; XOR-swizzle dst chunks
__device__ __forceinline__ void tile_async(uint32_t sdst, const float* src,
                                           int ld, int kc, int tid) {
#pragma unroll
    for (int t = 0; t < 4; t++) {
        int idx = tid + t * 256;          // 0..1023 chunks
        int r = idx >> 3, j = idx & 7;
        uint32_t dst = sdst + (uint32_t)(((r << 3) + (j ^ (r & 7))) << 4);
        const float* s = src + (size_t)r * ld + kc + j * 4;
        asm volatile("cp.async.cg.shared.global [%0], [%1], 16;" ::"r"(dst),
                     "l"(s));
    }
}

// fragment read: rows hold permuted k, chunks swizzled by row&7
__device__ __forceinline__ float4 frag(const float* tile, int r, int c2) {
    return *(const float4*)(tile + r * 32 + ((c2 ^ (r & 7)) << 2));
}

// one (A-tile x B-tile) accumulation pass over a 32-k chunk
__device__ __forceinline__ void gemm_pass(const float* As, const float* Bs,
                                          float acc[4][4][4], int wm, int wn,
                                          int g, int c) {
#pragma unroll
    for (int sp = 0; sp < 2; sp++) {
        float4 a[4][2], b[4];
        int c2 = 2 * c + sp;
#pragma unroll
        for (int mt = 0; mt < 4; mt++) {
            int r0 = wm + mt * 16 + g;
            a[mt][0] = frag(As, r0, c2);
            a[mt][1] = frag(As, r0 + 8, c2);
        }
#pragma unroll
        for (int nt = 0; nt < 4; nt++) b[nt] = frag(Bs, wn + nt * 8 + g, c2);
#pragma unroll
        for (int s = 0; s < 2; s++) {
#pragma unroll
            for (int mt = 0; mt < 4; mt++) {
                uint32_t a0 = __float_as_uint(s ? a[mt][0].z : a[mt][0].x);
                uint32_t a2 = __float_as_uint(s ? a[mt][0].w : a[mt][0].y);
                uint32_t a1 = __float_as_uint(s ? a[mt][1].z : a[mt][1].x);
                uint32_t a3 = __float_as_uint(s ? a[mt][1].w : a[mt][1].y);
#pragma unroll
                for (int nt = 0; nt < 4; nt++) {
                    uint32_t b0 = __float_as_uint(s ? b[nt].z : b[nt].x);
                    uint32_t b1 = __float_as_uint(s ? b[nt].w : b[nt].y);
                    mma8(acc[mt][nt], a0, a1, a2, a3, b0, b1);
                }
            }
        }
    }
}

// ---------------------------------------------------------------------------
// cp.async double-buffered mma.sync tf32 NT GEMM: C = A[M,K] @ B[N,K]^T (+bias)
// All k-dims in gmem are pre-permuted (permk). SPLIT: 3-product hi/lo.
// Clo != null : write tf32 hi/lo pair
// perm  != 0  : row r -> (r&7)*SS + z*256 + (r>>3)   (torch .view fold)
// permC != 0  : column k-permuted on store (output feeds a later GEMM's K dim)
// rndC  != 0  : round stored C to tf32
// ---------------------------------------------------------------------------
template <bool SPLIT>
__global__ void __launch_bounds__(256, SPLIT ? 1 : 2)
mm_gemm(const float* __restrict__ A0, const float* __restrict__ A1,
        const float* __restrict__ B0, const float* __restrict__ B1,
        const float* __restrict__ bias,
        float* __restrict__ C, float* __restrict__ Clo,
        int M, int N, int K, int lda, int ldb, int ldc,
        long aZ, long bZ, long cZ, int perm, int permC, int rndC) {
    extern __shared__ float smf[];
    const int NT = SPLIT ? 4 : 2;          // tiles per buffer
    const uint32_t sb = smem_u32(smf);

    const int tid = threadIdx.x;
    const int warp = tid >> 5, lane = tid & 31;
    const int g = lane >> 2, c = lane & 3;
    const int m0 = blockIdx.y * 128, n0 = blockIdx.x * 128;
    const int z = blockIdx.z;
    const int wm = (warp >> 2) * 64;
    const int wn = (warp & 3) * 32;

    const float* Ag = A0 + (size_t)z * aZ + (size_t)m0 * lda;
    const float* Bg = B0 + (size_t)z * bZ + (size_t)n0 * ldb;
    const float* Ag1 = SPLIT ? A1 + (size_t)z * aZ + (size_t)m0 * lda : nullptr;
    const float* Bg1 = SPLIT ? B1 + (size_t)z * bZ + (size_t)n0 * ldb : nullptr;

    float acc[4][4][4];
#pragma unroll
    for (int i = 0; i < 4; i++)
#pragma unroll
        for (int j = 0; j < 4; j++)
#pragma unroll
            for (int k = 0; k < 4; k++) acc[i][j][k] = 0.0f;

    // prologue: chunk 0 -> buffer 0
    {
        uint32_t b0s = sb;
        tile_async(b0s, Ag, lda, 0, tid);
        tile_async(b0s + TFL * 4, Bg, ldb, 0, tid);
        if (SPLIT) {
            tile_async(b0s + 2 * TFL * 4, Ag1, lda, 0, tid);
            tile_async(b0s + 3 * TFL * 4, Bg1, ldb, 0, tid);
        }
        asm volatile("cp.async.commit_group;");
    }

    int cur = 0;
    for (int kc = 0; kc < K; kc += 32) {
        if (kc + 32 < K) {
            uint32_t bs = sb + (uint32_t)((cur ^ 1) * NT * TFL * 4);
            tile_async(bs, Ag, lda, kc + 32, tid);
            tile_async(bs + TFL * 4, Bg, ldb, kc + 32, tid);
            if (SPLIT) {
                tile_async(bs + 2 * TFL * 4, Ag1, lda, kc + 32, tid);
                tile_async(bs + 3 * TFL * 4, Bg1, ldb, kc + 32, tid);
            }
            asm volatile("cp.async.commit_group;");
            asm volatile("cp.async.wait_group 1;");
        } else {
            asm volatile("cp.async.wait_group 0;");
        }
        __syncthreads();

        const float* Ahs = smf + cur * NT * TFL;
        const float* Bhs = Ahs + TFL;
        gemm_pass(Ahs, Bhs, acc, wm, wn, g, c);
        if (SPLIT) {
            const float* Als = Ahs + 2 * TFL;
            const float* Bls = Ahs + 3 * TFL;
            gemm_pass(Ahs, Bls, acc, wm, wn, g, c);
            gemm_pass(Als, Bhs, acc, wm, wn, g, c);
        }
        __syncthreads();
        cur ^= 1;
    }

    // epilogue
    float* Cb = C + (size_t)z * cZ;
    float* Lb = Clo ? Clo + (size_t)z * cZ : nullptr;
#pragma unroll
    for (int mt = 0; mt < 4; mt++) {
#pragma unroll
        for (int half = 0; half < 2; half++) {
            int row = m0 + wm + mt * 16 + g + half * 8;
            long crow = perm ? ((long)(row & 7) * SS + (long)z * 256 + (row >> 3))
                             : (long)row;
#pragma unroll
            for (int nt = 0; nt < 4; nt++) {
                int col = n0 + wn + nt * 8 + c * 2;
                float v0 = acc[mt][nt][half * 2 + 0];
                float v1 = acc[mt][nt][half * 2 + 1];
                if (bias) {
                    v0 += bias[col];
                    v1 += bias[col + 1];
                }
                long o0 = crow * ldc + (permC ? permk(col) : col);
                long o1 = crow * ldc + (permC ? permk(col + 1) : col + 1);
                if (Lb) {
                    float h0 = tf32_rna(v0), h1 = tf32_rna(v1);
                    Cb[o0] = h0;
                    Cb[o1] = h1;
                    Lb[o0] = tf32_rna(v0 - h0);
                    Lb[o1] = tf32_rna(v1 - h1);
                } else {
                    if (rndC) {
                        v0 = tf32_rna(v0);
                        v1 = tf32_rna(v1);
                    }
                    Cb[o0] = v0;
                    Cb[o1] = v1;
                }
            }
        }
    }
}

// ---------------- prep kernels (all write k-permuted) -----------------------
__global__ void relenc1_split(const float* __restrict__ rel4,
                              const float* __restrict__ w1,
                              const float* __restrict__ b1,
                              float* __restrict__ hi, float* __restrict__ lo) {
    int idx = blockIdx.x * 256 + threadIdx.x;
    int s = idx >> 10, j = idx & 1023;
    float acc = b1[j];
#pragma unroll
    for (int k = 0; k < 4; k++) acc = fmaf(rel4[s * 4 + k], w1[k * 1024 + j], acc);
    acc = fmaxf(acc, 0.0f);
    float h = tf32_rna(acc);
    int o = s * 1024 + permk(j);
    hi[o] = h;
    lo[o] = tf32_rna(acc - h);
}

__global__ void split_ew(const float* __restrict__ in, float* __restrict__ hi,
                         float* __restrict__ lo) {
    int i = blockIdx.x * 256 + threadIdx.x;
    float v = in[i];
    float h = tf32_rna(v);
    int o = permk(i);
    hi[o] = h;
    lo[o] = tf32_rna(v - h);
}

// out[c][permk(r)] = rna(in[r][c]) (+ lo if SPLIT). block (32,8), grid (C/32,R/32,Z)
template <bool SPLIT>
__global__ void transpose_k(const float* __restrict__ in, float* __restrict__ ohi,
                            float* __restrict__ olo, int R, int C) {
    __shared__ float t[32][33];
    size_t zo = (size_t)blockIdx.z * R * C;
    int r0 = blockIdx.y * 32, c0 = blockIdx.x * 32;
#pragma unroll
    for (int i = 0; i < 32; i += 8)
        t[threadIdx.y + i][threadIdx.x] =
            in[zo + (size_t)(r0 + threadIdx.y + i) * C + c0 + threadIdx.x];
    __syncthreads();
    int tx = threadIdx.x;
    int pr = ((tx & 3) << 3) | (tx >> 2);   // permk within the 32-group
#pragma unroll
    for (int i = 0; i < 32; i += 8) {
        float v = t[tx][threadIdx.y + i];
        size_t o = zo + (size_t)(c0 + threadIdx.y + i) * R + r0 + pr;
        if (SPLIT) {
            float h = tf32_rna(v);
            ohi[o] = h;
            olo[o] = tf32_rna(v - h);
        } else {
            ohi[o] = tf32_rna(v);
        }
    }
}

// ---------------- softmax: register-cached, writes tf32 probs k-permuted ----
__global__ void softmax_kernel(float* __restrict__ L) {
    float* p = L + (size_t)blockIdx.x * SS;
    const int tid = threadIdx.x;
    __shared__ float red[8];

    float4 v[2];
    v[0] = *(const float4*)&p[tid * 4];
    v[1] = *(const float4*)&p[1024 + tid * 4];

    float m = fmaxf(fmaxf(fmaxf(v[0].x, v[0].y), fmaxf(v[0].z, v[0].w)),
                    fmaxf(fmaxf(v[1].x, v[1].y), fmaxf(v[1].z, v[1].w)));
#pragma unroll
    for (int s = 16; s > 0; s >>= 1)
        m = fmaxf(m, __shfl_xor_sync(0xFFFFFFFF, m, s));
    if ((tid & 31) == 0) red[tid >> 5] = m;
    __syncthreads();
    m = fmaxf(fmaxf(fmaxf(red[0], red[1]), fmaxf(red[2], red[3])),
              fmaxf(fmaxf(red[4], red[5]), fmaxf(red[6], red[7])));
    __syncthreads();

    float sum = 0.0f;
#pragma unroll
    for (int h = 0; h < 2; h++) {
        float* f = (float*)&v[h];
#pragma unroll
        for (int e = 0; e < 4; e++) {
            f[e] = __expf(f[e] - m);
            sum += f[e];
        }
    }
#pragma unroll
    for (int s = 16; s > 0; s >>= 1) sum += __shfl_xor_sync(0xFFFFFFFF, sum, s);
    if ((tid & 31) == 0) red[tid >> 5] = sum;
    __syncthreads();
    sum = red[0] + red[1] + red[2] + red[3] + red[4] + red[5] + red[6] + red[7];
    float inv = 1.0f / sum;
    __syncthreads();   // all reads of p done before permuted in-place writes

#pragma unroll
    for (int h = 0; h < 2; h++) {
        int cbase = h * 1024 + tid * 4;
        float* f = (float*)&v[h];
#pragma unroll
        for (int e = 0; e < 4; e++)
            p[permk(cbase + e)] = tf32_rna(f[e] * inv);
    }
}

// ---------------------------------------------------------------------------
extern "C" void kernel_launch(void* const* d_in, const int* in_sizes, int n_in,
                              void* d_out, int out_size) {
    const float* x         = (const float*)d_in[0];
    const float* relations = (const float*)d_in[1];
    const float* re_w1     = (const float*)d_in[2];
    const float* re_b1     = (const float*)d_in[3];
    const float* re_w2     = (const float*)d_in[4];
    const float* re_b2     = (const float*)d_in[5];
    const float* attn_w    = (const float*)d_in[6];
    const float* out_w     = (const float*)d_in[7];
    const float* out_b     = (const float*)d_in[8];
    float* out = (float*)d_out;

    float *hid_hi, *hid_lo, *w2t_hi, *w2t_lo, *awt_hi, *awt_lo;
    float *x_hi, *x_lo, *xt, *owt, *rel_hi, *rel_lo, *Q_hi, *Q_lo, *Lg, *ctx;
    cudaGetSymbolAddress((void**)&hid_hi, g_hid_hi);
    cudaGetSymbolAddress((void**)&hid_lo, g_hid_lo);
    cudaGetSymbolAddress((void**)&w2t_hi, g_w2t_hi);
    cudaGetSymbolAddress((void**)&w2t_lo, g_w2t_lo);
    cudaGetSymbolAddress((void**)&awt_hi, g_awt_hi);
    cudaGetSymbolAddress((void**)&awt_lo, g_awt_lo);
    cudaGetSymbolAddress((void**)&x_hi, g_x_hi);
    cudaGetSymbolAddress((void**)&x_lo, g_x_lo);
    cudaGetSymbolAddress((void**)&xt, g_xt);
    cudaGetSymbolAddress((void**)&owt, g_owt);
    cudaGetSymbolAddress((void**)&rel_hi, g_rel_hi);
    cudaGetSymbolAddress((void**)&rel_lo, g_rel_lo);
    cudaGetSymbolAddress((void**)&Q_hi, g_Q_hi);
    cudaGetSymbolAddress((void**)&Q_lo, g_Q_lo);
    cudaGetSymbolAddress((void**)&Lg, g_logits);
    cudaGetSymbolAddress((void**)&ctx, g_ctx);

    const int SM_SPLIT = 2 * 4 * TFL * 4;   // 131072 B (double-buffered, 4 tiles)
    const int SM_PLAIN = 2 * 2 * TFL * 4;   // 65536 B
    cudaFuncSetAttribute(mm_gemm<true>, cudaFuncAttributeMaxDynamicSharedMemorySize,
                         SM_SPLIT);
    cudaFuncSetAttribute(mm_gemm<false>, cudaFuncAttributeMaxDynamicSharedMemorySize,
                         SM_PLAIN);

    // ---- prep (all outputs k-permuted)
    relenc1_split<<<(SS * DD) / 256, 256>>>(relations, re_w1, re_b1, hid_hi, hid_lo);
    transpose_k<true><<<dim3(32, 32, 1), dim3(32, 8)>>>(re_w2, w2t_hi, w2t_lo,
                                                        1024, 1024);
    transpose_k<true><<<dim3(32, 32, 8), dim3(32, 8)>>>(attn_w, awt_hi, awt_lo,
                                                        1024, 1024);
    split_ew<<<(SS * DD) / 256, 256>>>(x, x_hi, x_lo);
    transpose_k<false><<<dim3(32, 64, 1), dim3(32, 8)>>>(x, xt, nullptr, 2048, 1024);
    transpose_k<false><<<dim3(32, 256, 1), dim3(32, 8)>>>(out_w, owt, nullptr,
                                                          8192, 1024);

    // ---- stage 2: rel = hid @ re_w2 + b2 (split out, permC: feeds stage-4 K)
    mm_gemm<true><<<dim3(8, 16, 1), 256, SM_SPLIT>>>(
        hid_hi, hid_lo, w2t_hi, w2t_lo, re_b2, rel_hi, rel_lo,
        SS, DD, DD, DD, DD, DD, 0, 0, 0, 0, 1, 0);

    // ---- stage 3: Q[h] = x @ attn_w[h] (perm rows + permC, split out)
    mm_gemm<true><<<dim3(8, 16, 8), 256, SM_SPLIT>>>(
        x_hi, x_lo, awt_hi, awt_lo, nullptr, Q_hi, Q_lo,
        SS, DD, DD, DD, DD, DD, 0, (long)DD * DD, 0, 1, 1, 0);

    // ---- stage 4: logits[h2] = rel @ Q[h2]^T (natural C)
    mm_gemm<true><<<dim3(16, 16, 8), 256, SM_SPLIT>>>(
        rel_hi, rel_lo, Q_hi, Q_lo, nullptr, Lg, nullptr,
        SS, SS, DD, DD, DD, SS, 0, (long)SS * DD, (long)SS * SS, 0, 0, 0);

    // ---- stage 5: softmax (rounds + k-permutes probs for stage 6)
    softmax_kernel<<<HH * SS, 256>>>(Lg);

    // ---- stage 6: ctx[:, h*D:(h+1)*D] = attn[h] @ x (rnd + permC for stage-7 K)
    mm_gemm<false><<<dim3(8, 16, 8), 256, SM_PLAIN>>>(
        Lg, nullptr, xt, nullptr, nullptr, ctx, nullptr,
        SS, DD, SS, SS, SS, HH * DD, (long)SS * SS, 0, (long)DD, 0, 1, 1);

    // ---- stage 7: out = ctx @ out_w + b (natural C)
    mm_gemm<false><<<dim3(8, 16, 1), 256, SM_PLAIN>>>(
        ctx, nullptr, owt, nullptr, out_b, out, nullptr,
        SS, DD, HH * DD, HH * DD, HH * DD, DD, 0, 0, 0, 0, 0, 0);
}

// round 12
// speedup vs baseline: 2.5254x; 1.0056x over previous
#include <cuda_runtime.h>
#include <cstdint>
#include <math.h>

#define SS 2048
#define DD 1024
#define HH 8

// ---------------- scratch (__device__ globals; allocation-free rule) -------
__device__ float g_hid_hi[SS * DD];
__device__ float g_hid_lo[SS * DD];
__device__ float g_w2t_hi[DD * DD];
__device__ float g_w2t_lo[DD * DD];
__device__ float g_awt_hi[HH * DD * DD];
__device__ float g_awt_lo[HH * DD * DD];
__device__ float g_x_hi[SS * DD];
__device__ float g_x_lo[SS * DD];
__device__ float g_xt[DD * SS];
__device__ float g_owt[DD * HH * DD];
__device__ float g_rel_hi[SS * DD];
__device__ float g_rel_lo[SS * DD];
__device__ float g_Q_hi[HH * SS * DD];
__device__ float g_Q_lo[HH * SS * DD];
__device__ float g_logits[(size_t)HH * SS * SS];
__device__ float g_ctx[(size_t)SS * HH * DD];

// ---------------- helpers ---------------------------------------------------
__device__ __forceinline__ float tf32_rna(float x) {
    uint32_t u;
    asm("cvt.rna.tf32.f32 %0, %1;" : "=r"(u) : "f"(x));
    return __uint_as_float(u);
}
__device__ __forceinline__ uint32_t smem_u32(const void* p) {
    uint32_t a;
    asm("{ .reg .u64 t; cvta.to.shared.u64 t, %1; cvt.u32.u64 %0, t; }"
        : "=r"(a) : "l"(p));
    return a;
}
__device__ __forceinline__ void mma8(float* d, uint32_t a0, uint32_t a1,
                                     uint32_t a2, uint32_t a3, uint32_t b0,
                                     uint32_t b1) {
    asm volatile(
        "mma.sync.aligned.m16n8k8.row.col.f32.tf32.tf32.f32 "
        "{%0,%1,%2,%3},{%4,%5,%6,%7},{%8,%9},{%0,%1,%2,%3};"
        : "+f"(d[0]), "+f"(d[1]), "+f"(d[2]), "+f"(d[3])
        : "r"(a0), "r"(a1), "r"(a2), "r"(a3), "r"(b0), "r"(b1));
}

#define TFL (128 * 32)   // floats per 128x32 tile (16 KB)
#define SROW 132         // staging row stride (floats)

// async-copy one 128x32 tile; gmem is k-pre-permuted; XOR-swizzle dst chunks
__device__ __forceinline__ void tile_async(uint32_t sdst, const float* src,
                                           int ld, int kc, int tid) {
#pragma unroll
    for (int t = 0; t < 4; t++) {
        int idx = tid + t * 256;          // 0..1023 chunks
        int r = idx >> 3, j = idx & 7;
        uint32_t dst = sdst + (uint32_t)(((r << 3) + (j ^ (r & 7))) << 4);
        const float* s = src + (size_t)r * ld + kc + j * 4;
        asm volatile("cp.async.cg.shared.global [%0], [%1], 16;" ::"r"(dst),
                     "l"(s));
    }
}

// fragment read: rows hold permuted k, chunks swizzled by row&7
__device__ __forceinline__ float4 frag(const float* tile, int r, int c2) {
    return *(const float4*)(tile + r * 32 + ((c2 ^ (r & 7)) << 2));
}

// one (A-tile x B-tile) accumulation pass over a 32-k chunk
__device__ __forceinline__ void gemm_pass(const float* As, const float* Bs,
                                          float acc[4][4][4], int wm, int wn,
                                          int g, int c) {
#pragma unroll
    for (int sp = 0; sp < 2; sp++) {
        float4 a[4][2], b[4];
        int c2 = 2 * c + sp;
#pragma unroll
        for (int mt = 0; mt < 4; mt++) {
            int r0 = wm + mt * 16 + g;
            a[mt][0] = frag(As, r0, c2);
            a[mt][1] = frag(As, r0 + 8, c2);
        }
#pragma unroll
        for (int nt = 0; nt < 4; nt++) b[nt] = frag(Bs, wn + nt * 8 + g, c2);
#pragma unroll
        for (int s = 0; s < 2; s++) {
#pragma unroll
            for (int mt = 0; mt < 4; mt++) {
                uint32_t a0 = __float_as_uint(s ? a[mt][0].z : a[mt][0].x);
                uint32_t a2 = __float_as_uint(s ? a[mt][0].w : a[mt][0].y);
                uint32_t a1 = __float_as_uint(s ? a[mt][1].z : a[mt][1].x);
                uint32_t a3 = __float_as_uint(s ? a[mt][1].w : a[mt][1].y);
#pragma unroll
                for (int nt = 0; nt < 4; nt++) {
                    uint32_t b0 = __float_as_uint(s ? b[nt].z : b[nt].x);
                    uint32_t b1 = __float_as_uint(s ? b[nt].w : b[nt].y);
                    mma8(acc[mt][nt], a0, a1, a2, a3, b0, b1);
                }
            }
        }
    }
}

// ---------------------------------------------------------------------------
// cp.async double-buffered mma.sync tf32 NT GEMM: C = A[M,K] @ B[N,K]^T (+bias)
// All k-dims in gmem are pre-permuted (permk). SPLIT: 3-product hi/lo.
// Epilogue stages accumulators through smem so that ALL gmem stores are
// coalesced float4, with the row-perm and column k-perm applied on smem read.
// ---------------------------------------------------------------------------
template <bool SPLIT>
__global__ void __launch_bounds__(256, SPLIT ? 1 : 2)
mm_gemm(const float* __restrict__ A0, const float* __restrict__ A1,
        const float* __restrict__ B0, const float* __restrict__ B1,
        const float* __restrict__ bias,
        float* __restrict__ C, float* __restrict__ Clo,
        int M, int N, int K, int lda, int ldb, int ldc,
        long aZ, long bZ, long cZ, int perm, int permC, int rndC) {
    extern __shared__ float smf[];
    const int NT = SPLIT ? 4 : 2;          // tiles per buffer
    const uint32_t sb = smem_u32(smf);

    const int tid = threadIdx.x;
    const int warp = tid >> 5, lane = tid & 31;
    const int g = lane >> 2, c = lane & 3;
    const int m0 = blockIdx.y * 128, n0 = blockIdx.x * 128;
    const int z = blockIdx.z;
    const int wm = (warp >> 2) * 64;
    const int wn = (warp & 3) * 32;

    const float* Ag = A0 + (size_t)z * aZ + (size_t)m0 * lda;
    const float* Bg = B0 + (size_t)z * bZ + (size_t)n0 * ldb;
    const float* Ag1 = SPLIT ? A1 + (size_t)z * aZ + (size_t)m0 * lda : nullptr;
    const float* Bg1 = SPLIT ? B1 + (size_t)z * bZ + (size_t)n0 * ldb : nullptr;

    float acc[4][4][4];
#pragma unroll
    for (int i = 0; i < 4; i++)
#pragma unroll
        for (int j = 0; j < 4; j++)
#pragma unroll
            for (int k = 0; k < 4; k++) acc[i][j][k] = 0.0f;

    // prologue: chunk 0 -> buffer 0
    {
        tile_async(sb, Ag, lda, 0, tid);
        tile_async(sb + TFL * 4, Bg, ldb, 0, tid);
        if (SPLIT) {
            tile_async(sb + 2 * TFL * 4, Ag1, lda, 0, tid);
            tile_async(sb + 3 * TFL * 4, Bg1, ldb, 0, tid);
        }
        asm volatile("cp.async.commit_group;");
    }

    int cur = 0;
    for (int kc = 0; kc < K; kc += 32) {
        if (kc + 32 < K) {
            uint32_t bs = sb + (uint32_t)((cur ^ 1) * NT * TFL * 4);
            tile_async(bs, Ag, lda, kc + 32, tid);
            tile_async(bs + TFL * 4, Bg, ldb, kc + 32, tid);
            if (SPLIT) {
                tile_async(bs + 2 * TFL * 4, Ag1, lda, kc + 32, tid);
                tile_async(bs + 3 * TFL * 4, Bg1, ldb, kc + 32, tid);
            }
            asm volatile("cp.async.commit_group;");
            asm volatile("cp.async.wait_group 1;");
        } else {
            asm volatile("cp.async.wait_group 0;");
        }
        __syncthreads();

        const float* Ahs = smf + cur * NT * TFL;
        const float* Bhs = Ahs + TFL;
        gemm_pass(Ahs, Bhs, acc, wm, wn, g, c);
        if (SPLIT) {
            const float* Als = Ahs + 2 * TFL;
            const float* Bls = Ahs + 3 * TFL;
            gemm_pass(Ahs, Bls, acc, wm, wn, g, c);
            gemm_pass(Als, Bhs, acc, wm, wn, g, c);
        }
        __syncthreads();
        cur ^= 1;
    }

    // ---- staged epilogue: coalesced float4 stores --------------------------
    float* stage = smf;                    // 64 x SROW floats (fits both cfgs)
    float* Cb = C + (size_t)z * cZ;
    float* Lb = Clo ? Clo + (size_t)z * cZ : nullptr;
    const int nRounds = Clo ? 2 : 1;

#pragma unroll 1
    for (int h128 = 0; h128 < 2; h128++) {        // rows 0..63 then 64..127
#pragma unroll 1
        for (int rnd = 0; rnd < nRounds; rnd++) {
            __syncthreads();
            if ((warp >> 2) == h128) {
#pragma unroll
                for (int mt = 0; mt < 4; mt++)
#pragma unroll
                    for (int hf = 0; hf < 2; hf++) {
                        int lrow = mt * 16 + g + hf * 8;   // 0..63
#pragma unroll
                        for (int nt = 0; nt < 4; nt++) {
                            int col = wn + nt * 8 + c * 2;
                            float v0 = acc[mt][nt][hf * 2 + 0];
                            float v1 = acc[mt][nt][hf * 2 + 1];
                            if (bias) {
                                v0 += bias[n0 + col];
                                v1 += bias[n0 + col + 1];
                            }
                            if (Clo) {
                                float h0 = tf32_rna(v0), h1 = tf32_rna(v1);
                                if (rnd == 0) {
                                    v0 = h0;
                                    v1 = h1;
                                } else {
                                    v0 = tf32_rna(v0 - h0);
                                    v1 = tf32_rna(v1 - h1);
                                }
                            } else if (rndC) {
                                v0 = tf32_rna(v0);
                                v1 = tf32_rna(v1);
                            }
                            stage[lrow * SROW + col] = v0;
                            stage[lrow * SROW + col + 1] = v1;
                        }
                    }
            }
            __syncthreads();
            float* Ob = (rnd == 0) ? Cb : Lb;
#pragma unroll
            for (int i = 0; i < 8; i++) {
                int flat = tid + i * 256;
                int j = flat & 31;           // float4 column group
                int lrow = flat >> 5;        // 0..63
                int row = m0 + h128 * 64 + lrow;
                long crow =
                    perm ? ((long)(row & 7) * SS + (long)z * 256 + (row >> 3))
                         : (long)row;
                int p = j * 4;
                float4 v;
                if (permC) {
                    // dest col p+e takes src col k0+4e (inverse k-perm)
                    int q0 = p & 31;
                    int k0 = (p & ~31) + ((q0 & 7) << 2) + (q0 >> 3);
                    v.x = stage[lrow * SROW + k0];
                    v.y = stage[lrow * SROW + k0 + 4];
                    v.z = stage[lrow * SROW + k0 + 8];
                    v.w = stage[lrow * SROW + k0 + 12];
                } else {
                    v = *(const float4*)&stage[lrow * SROW + p];
                }
                *(float4*)&Ob[crow * ldc + n0 + p] = v;
            }
        }
    }
}

// ---------------- prep kernels (coalesced permuted stores via shuffles) -----
__global__ void relenc1_split(const float* __restrict__ rel4,
                              const float* __restrict__ w1,
                              const float* __restrict__ b1,
                              float* __restrict__ hi, float* __restrict__ lo) {
    int idx = blockIdx.x * 256 + threadIdx.x;
    int s = idx >> 10, j = idx & 1023;
    float acc = b1[j];
#pragma unroll
    for (int k = 0; k < 4; k++) acc = fmaf(rel4[s * 4 + k], w1[k * 1024 + j], acc);
    acc = fmaxf(acc, 0.0f);
    float h = tf32_rna(acc);
    float l = tf32_rna(acc - h);
    int lane = threadIdx.x & 31;
    int src = ((lane & 7) << 2) | (lane >> 3);   // inverse k-perm
    float hw = __shfl_sync(0xFFFFFFFF, h, src);
    float lw = __shfl_sync(0xFFFFFFFF, l, src);
    int o = s * 1024 + j;
    hi[o] = hw;
    lo[o] = lw;
}

__global__ void split_ew(const float* __restrict__ in, float* __restrict__ hi,
                         float* __restrict__ lo) {
    int i = blockIdx.x * 256 + threadIdx.x;
    float v = in[i];
    float h = tf32_rna(v);
    float l = tf32_rna(v - h);
    int lane = threadIdx.x & 31;
    int src = ((lane & 7) << 2) | (lane >> 3);
    hi[i] = __shfl_sync(0xFFFFFFFF, h, src);
    lo[i] = __shfl_sync(0xFFFFFFFF, l, src);
}

// out[c][permuted r] via inverse-indexed smem read; stores fully coalesced
template <bool SPLIT>
__global__ void transpose_k(const float* __restrict__ in, float* __restrict__ ohi,
                            float* __restrict__ olo, int R, int C) {
    __shared__ float t[32][33];
    size_t zo = (size_t)blockIdx.z * R * C;
    int r0 = blockIdx.y * 32, c0 = blockIdx.x * 32;
#pragma unroll
    for (int i = 0; i < 32; i += 8)
        t[threadIdx.y + i][threadIdx.x] =
            in[zo + (size_t)(r0 + threadIdx.y + i) * C + c0 + threadIdx.x];
    __syncthreads();
    int tx = threadIdx.x;
    int sx = ((tx & 7) << 2) | (tx >> 3);   // inverse k-perm source row
#pragma unroll
    for (int i = 0; i < 32; i += 8) {
        float v = t[sx][threadIdx.y + i];
        size_t o = zo + (size_t)(c0 + threadIdx.y + i) * R + r0 + tx;
        if (SPLIT) {
            float h = tf32_rna(v);
            ohi[o] = h;
            olo[o] = tf32_rna(v - h);
        } else {
            ohi[o] = tf32_rna(v);
        }
    }
}

// ---------------- softmax: register-cached, coalesced permuted store --------
__global__ void softmax_kernel(float* __restrict__ L) {
    float* p = L + (size_t)blockIdx.x * SS;
    const int tid = threadIdx.x;
    __shared__ float red[8];
    __shared__ float sbuf[SS];

    float4 v[2];
    v[0] = *(const float4*)&p[tid * 4];
    v[1] = *(const float4*)&p[1024 + tid * 4];

    float m = fmaxf(fmaxf(fmaxf(v[0].x, v[0].y), fmaxf(v[0].z, v[0].w)),
                    fmaxf(fmaxf(v[1].x, v[1].y), fmaxf(v[1].z, v[1].w)));
#pragma unroll
    for (int s = 16; s > 0; s >>= 1)
        m = fmaxf(m, __shfl_xor_sync(0xFFFFFFFF, m, s));
    if ((tid & 31) == 0) red[tid >> 5] = m;
    __syncthreads();
    m = fmaxf(fmaxf(fmaxf(red[0], red[1]), fmaxf(red[2], red[3])),
              fmaxf(fmaxf(red[4], red[5]), fmaxf(red[6], red[7])));
    __syncthreads();

    float sum = 0.0f;
#pragma unroll
    for (int h = 0; h < 2; h++) {
        float* f = (float*)&v[h];
#pragma unroll
        for (int e = 0; e < 4; e++) {
            f[e] = __expf(f[e] - m);
            sum += f[e];
        }
    }
#pragma unroll
    for (int s = 16; s > 0; s >>= 1) sum += __shfl_xor_sync(0xFFFFFFFF, sum, s);
    if ((tid & 31) == 0) red[tid >> 5] = sum;
    __syncthreads();
    sum = red[0] + red[1] + red[2] + red[3] + red[4] + red[5] + red[6] + red[7];
    float inv = 1.0f / sum;

    // stage tf32 probs in smem (natural order)
#pragma unroll
    for (int h = 0; h < 2; h++) {
        float* f = (float*)&v[h];
#pragma unroll
        for (int e = 0; e < 4; e++)
            sbuf[h * 1024 + tid * 4 + e] = tf32_rna(f[e] * inv);
    }
    __syncthreads();   // also orders all gmem reads before in-place writes

    // coalesced permuted flush: dest p0+e <- src k0+4e
#pragma unroll
    for (int it = 0; it < 2; it++) {
        int p0 = (tid + it * 256) * 4;
        int q0 = p0 & 31;
        int k0 = (p0 & ~31) + ((q0 & 7) << 2) + (q0 >> 3);
        float4 o;
        o.x = sbuf[k0];
        o.y = sbuf[k0 + 4];
        o.z = sbuf[k0 + 8];
        o.w = sbuf[k0 + 12];
        *(float4*)&p[p0] = o;
    }
}

// ---------------------------------------------------------------------------
extern "C" void kernel_launch(void* const* d_in, const int* in_sizes, int n_in,
                              void* d_out, int out_size) {
    const float* x         = (const float*)d_in[0];
    const float* relations = (const float*)d_in[1];
    const float* re_w1     = (const float*)d_in[2];
    const float* re_b1     = (const float*)d_in[3];
    const float* re_w2     = (const float*)d_in[4];
    const float* re_b2     = (const float*)d_in[5];
    const float* attn_w    = (const float*)d_in[6];
    const float* out_w     = (const float*)d_in[7];
    const float* out_b     = (const float*)d_in[8];
    float* out = (float*)d_out;

    float *hid_hi, *hid_lo, *w2t_hi, *w2t_lo, *awt_hi, *awt_lo;
    float *x_hi, *x_lo, *xt, *owt, *rel_hi, *rel_lo, *Q_hi, *Q_lo, *Lg, *ctx;
    cudaGetSymbolAddress((void**)&hid_hi, g_hid_hi);
    cudaGetSymbolAddress((void**)&hid_lo, g_hid_lo);
    cudaGetSymbolAddress((void**)&w2t_hi, g_w2t_hi);
    cudaGetSymbolAddress((void**)&w2t_lo, g_w2t_lo);
    cudaGetSymbolAddress((void**)&awt_hi, g_awt_hi);
    cudaGetSymbolAddress((void**)&awt_lo, g_awt_lo);
    cudaGetSymbolAddress((void**)&x_hi, g_x_hi);
    cudaGetSymbolAddress((void**)&x_lo, g_x_lo);
    cudaGetSymbolAddress((void**)&xt, g_xt);
    cudaGetSymbolAddress((void**)&owt, g_owt);
    cudaGetSymbolAddress((void**)&rel_hi, g_rel_hi);
    cudaGetSymbolAddress((void**)&rel_lo, g_rel_lo);
    cudaGetSymbolAddress((void**)&Q_hi, g_Q_hi);
    cudaGetSymbolAddress((void**)&Q_lo, g_Q_lo);
    cudaGetSymbolAddress((void**)&Lg, g_logits);
    cudaGetSymbolAddress((void**)&ctx, g_ctx);

    const int SM_SPLIT = 2 * 4 * TFL * 4;   // 131072 B
    const int SM_PLAIN = 2 * 2 * TFL * 4;   // 65536 B
    cudaFuncSetAttribute(mm_gemm<true>, cudaFuncAttributeMaxDynamicSharedMemorySize,
                         SM_SPLIT);
    cudaFuncSetAttribute(mm_gemm<false>, cudaFuncAttributeMaxDynamicSharedMemorySize,
                         SM_PLAIN);

    // ---- prep (all outputs k-permuted, coalesced stores)
    relenc1_split<<<(SS * DD) / 256, 256>>>(relations, re_w1, re_b1, hid_hi, hid_lo);
    transpose_k<true><<<dim3(32, 32, 1), dim3(32, 8)>>>(re_w2, w2t_hi, w2t_lo,
                                                        1024, 1024);
    transpose_k<true><<<dim3(32, 32, 8), dim3(32, 8)>>>(attn_w, awt_hi, awt_lo,
                                                        1024, 1024);
    split_ew<<<(SS * DD) / 256, 256>>>(x, x_hi, x_lo);
    transpose_k<false><<<dim3(32, 64, 1), dim3(32, 8)>>>(x, xt, nullptr, 2048, 1024);
    transpose_k<false><<<dim3(32, 256, 1), dim3(32, 8)>>>(out_w, owt, nullptr,
                                                          8192, 1024);

    // ---- stage 2: rel = hid @ re_w2 + b2 (split out, permC: feeds stage-4 K)
    mm_gemm<true><<<dim3(8, 16, 1), 256, SM_SPLIT>>>(
        hid_hi, hid_lo, w2t_hi, w2t_lo, re_b2, rel_hi, rel_lo,
        SS, DD, DD, DD, DD, DD, 0, 0, 0, 0, 1, 0);

    // ---- stage 3: Q[h] = x @ attn_w[h] (perm rows + permC, split out)
    mm_gemm<true><<<dim3(8, 16, 8), 256, SM_SPLIT>>>(
        x_hi, x_lo, awt_hi, awt_lo, nullptr, Q_hi, Q_lo,
        SS, DD, DD, DD, DD, DD, 0, (long)DD * DD, 0, 1, 1, 0);

    // ---- stage 4: logits[h2] = rel @ Q[h2]^T (natural C)
    mm_gemm<true><<<dim3(16, 16, 8), 256, SM_SPLIT>>>(
        rel_hi, rel_lo, Q_hi, Q_lo, nullptr, Lg, nullptr,
        SS, SS, DD, DD, DD, SS, 0, (long)SS * DD, (long)SS * SS, 0, 0, 0);

    // ---- stage 5: softmax (rounds + k-permutes probs for stage 6)
    softmax_kernel<<<HH * SS, 256>>>(Lg);

    // ---- stage 6: ctx[:, h*D:(h+1)*D] = attn[h] @ x (rnd + permC for stage-7 K)
    mm_gemm<false><<<dim3(8, 16, 8), 256, SM_PLAIN>>>(
        Lg, nullptr, xt, nullptr, nullptr, ctx, nullptr,
        SS, DD, SS, SS, SS, HH * DD, (long)SS * SS, 0, (long)DD, 0, 1, 1);

    // ---- stage 7: out = ctx @ out_w + b (natural C)
    mm_gemm<false><<<dim3(8, 16, 1), 256, SM_PLAIN>>>(
        ctx, nullptr, owt, nullptr, out_b, out, nullptr,
        SS, DD, HH * DD, HH * DD, HH * DD, DD, 0, 0, 0, 0, 0, 0);
}

// round 13
// speedup vs baseline: 4.3893x; 1.7381x over previous
#include <cuda_runtime.h>
#include <cuda_fp16.h>
#include <cstdint>
#include <math.h>

#define SS 2048
#define DD 1024
#define HH 8

// ---------------- scratch (__device__ globals; allocation-free rule) -------
__device__ __half g_hid_hi[SS * DD];
__device__ __half g_hid_lo[SS * DD];
__device__ __half g_w2t_hi[DD * DD];
__device__ __half g_w2t_lo[DD * DD];
__device__ __half g_awt_hi[HH * DD * DD];
__device__ __half g_awt_lo[HH * DD * DD];
__device__ __half g_x_hi[SS * DD];
__device__ __half g_x_lo[SS * DD];
__device__ __half g_xt[DD * SS];
__device__ __half g_owt[DD * HH * DD];
__device__ __half g_rel_hi[SS * DD];
__device__ __half g_rel_lo[SS * DD];
__device__ __half g_Q_hi[HH * SS * DD];
__device__ __half g_Q_lo[HH * SS * DD];
__device__ float  g_logits[(size_t)HH * SS * SS];
__device__ __half g_probs[(size_t)HH * SS * SS];
__device__ __half g_ctx[(size_t)SS * HH * DD];

// ---------------- helpers ---------------------------------------------------
__device__ __forceinline__ uint32_t smem_u32(const void* p) {
    uint32_t a;
    asm("{ .reg .u64 t; cvta.to.shared.u64 t, %1; cvt.u32.u64 %0, t; }"
        : "=r"(a) : "l"(p));
    return a;
}
// k-permutation (within 32-groups) for fp16 m16n8k16 fragments:
//   pos(k) = ((k&6)<<2) | (k&1) | ((k&8)>>2) | ((k&16)>>2)
// inverse: natural k stored at position p
__device__ __forceinline__ int invp(int p) {            // p in [0,32)
    return (p & 1) | (((p >> 3) & 3) << 1) | (((p >> 1) & 1) << 3) |
           (((p >> 2) & 1) << 4);
}
__device__ __forceinline__ uint32_t pack2(float x, float y) {
    __half hx = __float2half_rn(x), hy = __float2half_rn(y);
    return (uint32_t)__half_as_ushort(hx) |
           ((uint32_t)__half_as_ushort(hy) << 16);
}
__device__ __forceinline__ float lo_of(float v) {
    return v - __half2float(__float2half_rn(v));
}
__device__ __forceinline__ void mma16(float* d, uint32_t a0, uint32_t a1,
                                      uint32_t a2, uint32_t a3, uint32_t b0,
                                      uint32_t b1) {
    asm volatile(
        "mma.sync.aligned.m16n8k16.row.col.f32.f16.f16.f32 "
        "{%0,%1,%2,%3},{%4,%5,%6,%7},{%8,%9},{%0,%1,%2,%3};"
        : "+f"(d[0]), "+f"(d[1]), "+f"(d[2]), "+f"(d[3])
        : "r"(a0), "r"(a1), "r"(a2), "r"(a3), "r"(b0), "r"(b1));
}

#define TBYTES 16384          // one 128-row x 64-k half tile
#define TU32 4096             // same tile in uint32s
#define SROW 132              // fp32 staging row stride (floats)

// async-copy one 128x64-half tile (128B/row); gmem k-pre-permuted; XOR swizzle
__device__ __forceinline__ void tile_async_h(uint32_t sdst, const __half* src,
                                             int ldh, int kc, int tid) {
#pragma unroll
    for (int t = 0; t < 4; t++) {
        int idx = tid + t * 256;          // 0..1023 16B chunks
        int r = idx >> 3, j = idx & 7;
        uint32_t dst = sdst + (uint32_t)(((r << 3) + (j ^ (r & 7))) << 4);
        const __half* s = src + (size_t)r * ldh + kc + j * 8;
        asm volatile("cp.async.cg.shared.global [%0], [%1], 16;" ::"r"(dst),
                     "l"(s));
    }
}

// fragment read: 16B = the 8 operand halves a lane needs for 2 k16-mmas
__device__ __forceinline__ uint4 fragh(const uint32_t* tile, int r, int j) {
    return *(const uint4*)(tile + r * 32 + ((j ^ (r & 7)) << 2));
}

// plain pass: one (A x B) over a 64-k chunk
__device__ __forceinline__ void pass_h(const uint32_t* As, const uint32_t* Bs,
                                       float acc[4][4][4], int wm, int wn,
                                       int g, int c) {
#pragma unroll
    for (int sp = 0; sp < 2; sp++) {
        int j = sp * 4 + c;
        uint4 a0[4], a1[4], bb[4];
#pragma unroll
        for (int mt = 0; mt < 4; mt++) {
            int r0 = wm + mt * 16 + g;
            a0[mt] = fragh(As, r0, j);
            a1[mt] = fragh(As, r0 + 8, j);
        }
#pragma unroll
        for (int nt = 0; nt < 4; nt++) bb[nt] = fragh(Bs, wn + nt * 8 + g, j);
#pragma unroll
        for (int kk = 0; kk < 2; kk++)
#pragma unroll
            for (int mt = 0; mt < 4; mt++) {
                uint32_t A0 = kk ? a0[mt].z : a0[mt].x;
                uint32_t A2 = kk ? a0[mt].w : a0[mt].y;
                uint32_t A1 = kk ? a1[mt].z : a1[mt].x;
                uint32_t A3 = kk ? a1[mt].w : a1[mt].y;
#pragma unroll
                for (int nt = 0; nt < 4; nt++) {
                    uint32_t B0 = kk ? bb[nt].z : bb[nt].x;
                    uint32_t B1 = kk ? bb[nt].w : bb[nt].y;
                    mma16(acc[mt][nt], A0, A1, A2, A3, B0, B1);
                }
            }
    }
}

// split pass with fragment reuse: loads hi+lo frags once, 3 MMA products
__device__ __forceinline__ void pass_split_h(
    const uint32_t* Ah, const uint32_t* Bh, const uint32_t* Al,
    const uint32_t* Bl, float acc[4][4][4], int wm, int wn, int g, int c) {
#pragma unroll
    for (int sp = 0; sp < 2; sp++) {
        int j = sp * 4 + c;
        uint4 ah0[4], ah1[4], al0[4], al1[4], bh[4], bl[4];
#pragma unroll
        for (int mt = 0; mt < 4; mt++) {
            int r0 = wm + mt * 16 + g;
            ah0[mt] = fragh(Ah, r0, j);
            ah1[mt] = fragh(Ah, r0 + 8, j);
            al0[mt] = fragh(Al, r0, j);
            al1[mt] = fragh(Al, r0 + 8, j);
        }
#pragma unroll
        for (int nt = 0; nt < 4; nt++) {
            int n = wn + nt * 8 + g;
            bh[nt] = fragh(Bh, n, j);
            bl[nt] = fragh(Bl, n, j);
        }
#pragma unroll
        for (int kk = 0; kk < 2; kk++)
#pragma unroll
            for (int mt = 0; mt < 4; mt++) {
                uint32_t H0 = kk ? ah0[mt].z : ah0[mt].x;
                uint32_t H2 = kk ? ah0[mt].w : ah0[mt].y;
                uint32_t H1 = kk ? ah1[mt].z : ah1[mt].x;
                uint32_t H3 = kk ? ah1[mt].w : ah1[mt].y;
                uint32_t L0 = kk ? al0[mt].z : al0[mt].x;
                uint32_t L2 = kk ? al0[mt].w : al0[mt].y;
                uint32_t L1 = kk ? al1[mt].z : al1[mt].x;
                uint32_t L3 = kk ? al1[mt].w : al1[mt].y;
#pragma unroll
                for (int nt = 0; nt < 4; nt++) {
                    uint32_t BH0 = kk ? bh[nt].z : bh[nt].x;
                    uint32_t BH1 = kk ? bh[nt].w : bh[nt].y;
                    uint32_t BL0 = kk ? bl[nt].z : bl[nt].x;
                    uint32_t BL1 = kk ? bl[nt].w : bl[nt].y;
                    mma16(acc[mt][nt], H0, H1, H2, H3, BH0, BH1);
                    mma16(acc[mt][nt], H0, H1, H2, H3, BL0, BL1);
                    mma16(acc[mt][nt], L0, L1, L2, L3, BH0, BH1);
                }
            }
    }
}

// ---------------------------------------------------------------------------
// fp16 m16n8k16 NT GEMM: C[M,N] = A[M,K] @ B[N,K]^T (+bias), cp.async 2-stage.
// Operand k-dims in gmem are pre-permuted. SPLIT: 3-product hi/lo limbs.
// outHalf: C (and Clo) are __half with column k-perm (feeds a later K dim);
// otherwise C is fp32 with natural columns.
// perm != 0: output row r -> (r&7)*SS + z*256 + (r>>3)   (torch .view fold)
// ---------------------------------------------------------------------------
template <bool SPLIT>
__global__ void __launch_bounds__(256, SPLIT ? 1 : 2)
hgemm(const __half* __restrict__ A0, const __half* __restrict__ A1,
      const __half* __restrict__ B0, const __half* __restrict__ B1,
      const float* __restrict__ bias, void* Cv, void* Clov,
      int M, int N, int K, int lda, int ldb, int ldc,
      long aZ, long bZ, long cZ, int perm, int outHalf) {
    extern __shared__ float smf[];
    uint32_t* smu = (uint32_t*)smf;
    const int NT = SPLIT ? 4 : 2;
    const uint32_t sb = smem_u32(smf);

    const int tid = threadIdx.x;
    const int warp = tid >> 5, lane = tid & 31;
    const int g = lane >> 2, c = lane & 3;
    const int m0 = blockIdx.y * 128, n0 = blockIdx.x * 128;
    const int z = blockIdx.z;
    const int wm = (warp >> 2) * 64;
    const int wn = (warp & 3) * 32;

    const __half* Ag = A0 + (size_t)z * aZ + (size_t)m0 * lda;
    const __half* Bg = B0 + (size_t)z * bZ + (size_t)n0 * ldb;
    const __half* Ag1 = SPLIT ? A1 + (size_t)z * aZ + (size_t)m0 * lda : nullptr;
    const __half* Bg1 = SPLIT ? B1 + (size_t)z * bZ + (size_t)n0 * ldb : nullptr;

    float acc[4][4][4];
#pragma unroll
    for (int i = 0; i < 4; i++)
#pragma unroll
        for (int j = 0; j < 4; j++)
#pragma unroll
            for (int k = 0; k < 4; k++) acc[i][j][k] = 0.0f;

    // prologue
    tile_async_h(sb, Ag, lda, 0, tid);
    tile_async_h(sb + TBYTES, Bg, ldb, 0, tid);
    if (SPLIT) {
        tile_async_h(sb + 2 * TBYTES, Ag1, lda, 0, tid);
        tile_async_h(sb + 3 * TBYTES, Bg1, ldb, 0, tid);
    }
    asm volatile("cp.async.commit_group;");

    int cur = 0;
    for (int kc = 0; kc < K; kc += 64) {
        if (kc + 64 < K) {
            uint32_t bs = sb + (uint32_t)((cur ^ 1) * NT * TBYTES);
            tile_async_h(bs, Ag, lda, kc + 64, tid);
            tile_async_h(bs + TBYTES, Bg, ldb, kc + 64, tid);
            if (SPLIT) {
                tile_async_h(bs + 2 * TBYTES, Ag1, lda, kc + 64, tid);
                tile_async_h(bs + 3 * TBYTES, Bg1, ldb, kc + 64, tid);
            }
            asm volatile("cp.async.commit_group;");
            asm volatile("cp.async.wait_group 1;");
        } else {
            asm volatile("cp.async.wait_group 0;");
        }
        __syncthreads();

        const uint32_t* Ah = smu + cur * NT * TU32;
        const uint32_t* Bh = Ah + TU32;
        if (SPLIT)
            pass_split_h(Ah, Bh, Ah + 2 * TU32, Ah + 3 * TU32, acc, wm, wn, g, c);
        else
            pass_h(Ah, Bh, acc, wm, wn, g, c);
        __syncthreads();
        cur ^= 1;
    }

    // ---- staged epilogue: stage fp32 once per half-tile, flush coalesced ---
    float* stage = smf;
#pragma unroll 1
    for (int h128 = 0; h128 < 2; h128++) {
        __syncthreads();
        if ((warp >> 2) == h128) {
#pragma unroll
            for (int mt = 0; mt < 4; mt++)
#pragma unroll
                for (int hf = 0; hf < 2; hf++) {
                    int lrow = mt * 16 + g + hf * 8;
#pragma unroll
                    for (int nt = 0; nt < 4; nt++) {
                        int col = wn + nt * 8 + c * 2;
                        float v0 = acc[mt][nt][hf * 2 + 0];
                        float v1 = acc[mt][nt][hf * 2 + 1];
                        if (bias) {
                            v0 += bias[n0 + col];
                            v1 += bias[n0 + col + 1];
                        }
                        stage[lrow * SROW + col] = v0;
                        stage[lrow * SROW + col + 1] = v1;
                    }
                }
        }
        __syncthreads();

        if (outHalf) {
            __half* Cb = (__half*)Cv + (size_t)z * cZ;
            __half* Lb = Clov ? (__half*)Clov + (size_t)z * cZ : nullptr;
            const int nR = Lb ? 2 : 1;
#pragma unroll 1
            for (int rnd = 0; rnd < nR; rnd++) {
                __half* Ob = rnd ? Lb : Cb;
#pragma unroll
                for (int i = 0; i < 4; i++) {
                    int flat = tid + i * 256;
                    int jg = flat & 15, lrow = flat >> 4;
                    int row = m0 + h128 * 64 + lrow;
                    long crow = perm ? ((long)(row & 7) * SS + (long)z * 256 +
                                        (row >> 3))
                                     : (long)row;
                    int p0 = jg * 8;
                    int cc = (p0 >> 3) & 3, base = p0 & ~31;
                    const float* sr = stage + lrow * SROW + base + 2 * cc;
                    float f[8];
                    f[0] = sr[0];  f[1] = sr[1];
                    f[2] = sr[8];  f[3] = sr[9];
                    f[4] = sr[16]; f[5] = sr[17];
                    f[6] = sr[24]; f[7] = sr[25];
                    if (rnd) {
#pragma unroll
                        for (int e = 0; e < 8; e++) f[e] = lo_of(f[e]);
                    }
                    uint4 o;
                    o.x = pack2(f[0], f[1]);
                    o.y = pack2(f[2], f[3]);
                    o.z = pack2(f[4], f[5]);
                    o.w = pack2(f[6], f[7]);
                    *(uint4*)&Ob[crow * (long)ldc + n0 + p0] = o;
                }
            }
        } else {
            float* Ob = (float*)Cv + (size_t)z * cZ;
#pragma unroll
            for (int i = 0; i < 8; i++) {
                int flat = tid + i * 256;
                int jg = flat & 31, lrow = flat >> 5;
                int row = m0 + h128 * 64 + lrow;
                long crow = perm ? ((long)(row & 7) * SS + (long)z * 256 +
                                    (row >> 3))
                                 : (long)row;
                float4 v = *(const float4*)&stage[lrow * SROW + jg * 4];
                *(float4*)&Ob[crow * (long)ldc + n0 + jg * 4] = v;
            }
        }
    }
}

// ---------------- prep kernels ----------------------------------------------
__global__ void relenc1_split(const float* __restrict__ rel4,
                              const float* __restrict__ w1,
                              const float* __restrict__ b1,
                              __half* __restrict__ hi, __half* __restrict__ lo) {
    int idx = blockIdx.x * 256 + threadIdx.x;
    int s = idx >> 10, p = idx & 1023;
    int j = (p & ~31) | invp(p & 31);
    float acc = b1[j];
#pragma unroll
    for (int k = 0; k < 4; k++) acc = fmaf(rel4[s * 4 + k], w1[k * 1024 + j], acc);
    acc = fmaxf(acc, 0.0f);
    __half h = __float2half_rn(acc);
    hi[idx] = h;
    lo[idx] = __float2half_rn(acc - __half2float(h));
}

// fused transpose for re_w2 (z=0) + attn_w (z=1..8): out[c][perm(r)] half pair
__global__ void transpose_wqa(const float* __restrict__ w2,
                              const float* __restrict__ aw,
                              __half* __restrict__ w2hi, __half* __restrict__ w2lo,
                              __half* __restrict__ awhi, __half* __restrict__ awlo) {
    __shared__ float t[32][33];
    int z = blockIdx.z;
    const float* in = (z == 0) ? w2 : aw + (size_t)(z - 1) * DD * DD;
    __half* ohi = (z == 0) ? w2hi : awhi + (size_t)(z - 1) * DD * DD;
    __half* olo = (z == 0) ? w2lo : awlo + (size_t)(z - 1) * DD * DD;
    int r0 = blockIdx.y * 32, c0 = blockIdx.x * 32;
#pragma unroll
    for (int i = 0; i < 32; i += 8)
        t[threadIdx.y + i][threadIdx.x] =
            in[(size_t)(r0 + threadIdx.y + i) * DD + c0 + threadIdx.x];
    __syncthreads();
    int tx = threadIdx.x, sx = invp(tx);
#pragma unroll
    for (int i = 0; i < 32; i += 8) {
        float v = t[sx][threadIdx.y + i];
        size_t o = (size_t)(c0 + threadIdx.y + i) * DD + r0 + tx;
        __half h = __float2half_rn(v);
        ohi[o] = h;
        olo[o] = __float2half_rn(v - __half2float(h));
    }
}

// fused x prep: x_hi/lo [S][perm D]  AND  xt [D][perm S]
__global__ void prep_x(const float* __restrict__ x, __half* __restrict__ xhi,
                       __half* __restrict__ xlo, __half* __restrict__ xt) {
    __shared__ float t[32][33];
    int r0 = blockIdx.y * 32, c0 = blockIdx.x * 32;   // r over S, c over D
#pragma unroll
    for (int i = 0; i < 32; i += 8)
        t[threadIdx.y + i][threadIdx.x] =
            x[(size_t)(r0 + threadIdx.y + i) * DD + c0 + threadIdx.x];
    __syncthreads();
    int tx = threadIdx.x, sx = invp(tx);
#pragma unroll
    for (int i = 0; i < 32; i += 8) {
        // split limbs, cols k-permuted
        float v = t[threadIdx.y + i][sx];
        size_t o = (size_t)(r0 + threadIdx.y + i) * DD + c0 + tx;
        __half h = __float2half_rn(v);
        xhi[o] = h;
        xlo[o] = __float2half_rn(v - __half2float(h));
        // transpose, rows(S)=k permuted
        float u = t[sx][threadIdx.y + i];
        xt[(size_t)(c0 + threadIdx.y + i) * SS + r0 + tx] = __float2half_rn(u);
    }
}

// out_w [8192,1024] -> owt [1024][perm 8192], single limb
__global__ void transpose_owt(const float* __restrict__ in,
                              __half* __restrict__ ot) {
    __shared__ float t[32][33];
    int r0 = blockIdx.y * 32, c0 = blockIdx.x * 32;
#pragma unroll
    for (int i = 0; i < 32; i += 8)
        t[threadIdx.y + i][threadIdx.x] =
            in[(size_t)(r0 + threadIdx.y + i) * DD + c0 + threadIdx.x];
    __syncthreads();
    int tx = threadIdx.x, sx = invp(tx);
#pragma unroll
    for (int i = 0; i < 32; i += 8)
        ot[(size_t)(c0 + threadIdx.y + i) * (HH * DD) + r0 + tx] =
            __float2half_rn(t[sx][threadIdx.y + i]);
}

// ---------------- softmax: fp32 logits -> half probs (k-permuted) -----------
__global__ void softmax_kernel(const float* __restrict__ L,
                               __half* __restrict__ P) {
    const float* p = L + (size_t)blockIdx.x * SS;
    __half* q = P + (size_t)blockIdx.x * SS;
    const int tid = threadIdx.x;
    __shared__ float red[8];
    __shared__ float sbuf[SS];

    float4 v[2];
    v[0] = *(const float4*)&p[tid * 4];
    v[1] = *(const float4*)&p[1024 + tid * 4];

    float m = fmaxf(fmaxf(fmaxf(v[0].x, v[0].y), fmaxf(v[0].z, v[0].w)),
                    fmaxf(fmaxf(v[1].x, v[1].y), fmaxf(v[1].z, v[1].w)));
#pragma unroll
    for (int s = 16; s > 0; s >>= 1)
        m = fmaxf(m, __shfl_xor_sync(0xFFFFFFFF, m, s));
    if ((tid & 31) == 0) red[tid >> 5] = m;
    __syncthreads();
    m = fmaxf(fmaxf(fmaxf(red[0], red[1]), fmaxf(red[2], red[3])),
              fmaxf(fmaxf(red[4], red[5]), fmaxf(red[6], red[7])));
    __syncthreads();

    float sum = 0.0f;
#pragma unroll
    for (int h = 0; h < 2; h++) {
        float* f = (float*)&v[h];
#pragma unroll
        for (int e = 0; e < 4; e++) {
            f[e] = __expf(f[e] - m);
            sum += f[e];
        }
    }
#pragma unroll
    for (int s = 16; s > 0; s >>= 1) sum += __shfl_xor_sync(0xFFFFFFFF, sum, s);
    if ((tid & 31) == 0) red[tid >> 5] = sum;
    __syncthreads();
    sum = red[0] + red[1] + red[2] + red[3] + red[4] + red[5] + red[6] + red[7];
    float inv = 1.0f / sum;

#pragma unroll
    for (int h = 0; h < 2; h++) {
        float* f = (float*)&v[h];
#pragma unroll
        for (int e = 0; e < 4; e++)
            sbuf[h * 1024 + tid * 4 + e] = f[e] * inv;
    }
    __syncthreads();

    // coalesced permuted half flush: 8 halfs per thread
    {
        int p0 = tid * 8;
        int cc = (p0 >> 3) & 3, base = p0 & ~31;
        const float* sr = sbuf + base + 2 * cc;
        uint4 o;
        o.x = pack2(sr[0], sr[1]);
        o.y = pack2(sr[8], sr[9]);
        o.z = pack2(sr[16], sr[17]);
        o.w = pack2(sr[24], sr[25]);
        *(uint4*)&q[p0] = o;
    }
}

// ---------------------------------------------------------------------------
extern "C" void kernel_launch(void* const* d_in, const int* in_sizes, int n_in,
                              void* d_out, int out_size) {
    const float* x         = (const float*)d_in[0];
    const float* relations = (const float*)d_in[1];
    const float* re_w1     = (const float*)d_in[2];
    const float* re_b1     = (const float*)d_in[3];
    const float* re_w2     = (const float*)d_in[4];
    const float* re_b2     = (const float*)d_in[5];
    const float* attn_w    = (const float*)d_in[6];
    const float* out_w     = (const float*)d_in[7];
    const float* out_b     = (const float*)d_in[8];
    float* out = (float*)d_out;

    __half *hid_hi, *hid_lo, *w2t_hi, *w2t_lo, *awt_hi, *awt_lo;
    __half *x_hi, *x_lo, *xt, *owt, *rel_hi, *rel_lo, *Q_hi, *Q_lo, *probs, *ctx;
    float* Lg;
    cudaGetSymbolAddress((void**)&hid_hi, g_hid_hi);
    cudaGetSymbolAddress((void**)&hid_lo, g_hid_lo);
    cudaGetSymbolAddress((void**)&w2t_hi, g_w2t_hi);
    cudaGetSymbolAddress((void**)&w2t_lo, g_w2t_lo);
    cudaGetSymbolAddress((void**)&awt_hi, g_awt_hi);
    cudaGetSymbolAddress((void**)&awt_lo, g_awt_lo);
    cudaGetSymbolAddress((void**)&x_hi, g_x_hi);
    cudaGetSymbolAddress((void**)&x_lo, g_x_lo);
    cudaGetSymbolAddress((void**)&xt, g_xt);
    cudaGetSymbolAddress((void**)&owt, g_owt);
    cudaGetSymbolAddress((void**)&rel_hi, g_rel_hi);
    cudaGetSymbolAddress((void**)&rel_lo, g_rel_lo);
    cudaGetSymbolAddress((void**)&Q_hi, g_Q_hi);
    cudaGetSymbolAddress((void**)&Q_lo, g_Q_lo);
    cudaGetSymbolAddress((void**)&Lg, g_logits);
    cudaGetSymbolAddress((void**)&probs, g_probs);
    cudaGetSymbolAddress((void**)&ctx, g_ctx);

    const int SM_SPLIT = 2 * 4 * TBYTES;   // 131072 B
    const int SM_PLAIN = 2 * 2 * TBYTES;   // 65536 B
    cudaFuncSetAttribute(hgemm<true>, cudaFuncAttributeMaxDynamicSharedMemorySize,
                         SM_SPLIT);
    cudaFuncSetAttribute(hgemm<false>, cudaFuncAttributeMaxDynamicSharedMemorySize,
                         SM_PLAIN);

    // 1) relation encoder stage 1 (half limbs, k-permuted over D)
    relenc1_split<<<(SS * DD) / 256, 256>>>(relations, re_w1, re_b1, hid_hi,
                                            hid_lo);
    // 2) fused transpose of re_w2 + attn_w (half limbs, k-permuted)
    transpose_wqa<<<dim3(32, 32, 9), dim3(32, 8)>>>(re_w2, attn_w, w2t_hi,
                                                    w2t_lo, awt_hi, awt_lo);
    // 3) stage 2: rel = hid @ re_w2 + b2 (split; half pair out, permC)
    hgemm<true><<<dim3(8, 16, 1), 256, SM_SPLIT>>>(
        hid_hi, hid_lo, w2t_hi, w2t_lo, re_b2, rel_hi, rel_lo,
        SS, DD, DD, DD, DD, DD, 0, 0, 0, 0, 1);
    // 4) fused x prep (split limbs + transposed xt)
    prep_x<<<dim3(32, 64), dim3(32, 8)>>>(x, x_hi, x_lo, xt);
    // 5) stage 3: Q[h] = x @ attn_w[h] (split; row-perm; half pair out)
    hgemm<true><<<dim3(8, 16, 8), 256, SM_SPLIT>>>(
        x_hi, x_lo, awt_hi, awt_lo, nullptr, Q_hi, Q_lo,
        SS, DD, DD, DD, DD, DD, 0, (long)DD * DD, 0, 1, 1);
    // 6) stage 4: logits[h2] = rel @ Q[h2]^T (split; fp32 natural out)
    hgemm<true><<<dim3(16, 16, 8), 256, SM_SPLIT>>>(
        rel_hi, rel_lo, Q_hi, Q_lo, nullptr, Lg, nullptr,
        SS, SS, DD, DD, DD, SS, 0, (long)SS * DD, (long)SS * SS, 0, 0);
    // 7) softmax -> half probs (k-permuted over t)
    softmax_kernel<<<HH * SS, 256>>>(Lg, probs);
    // 8) stage 6: ctx[:, h*D:] = attn[h] @ x (plain; half out, permC)
    hgemm<false><<<dim3(8, 16, 8), 256, SM_PLAIN>>>(
        probs, nullptr, xt, nullptr, nullptr, ctx, nullptr,
        SS, DD, SS, SS, SS, HH * DD, (long)SS * SS, 0, (long)DD, 0, 1);
    // 9) out_w transpose (half, k-permuted over H*D)
    transpose_owt<<<dim3(32, 256), dim3(32, 8)>>>(out_w, owt);
    // 10) stage 7: out = ctx @ out_w + b (plain; fp32 natural out)
    hgemm<false><<<dim3(8, 16, 1), 256, SM_PLAIN>>>(
        ctx, nullptr, owt, nullptr, out_b, out, nullptr,
        SS, DD, HH * DD, HH * DD, HH * DD, DD, 0, 0, 0, 0, 0);
}

// round 14
// speedup vs baseline: 4.4202x; 1.0070x over previous
#include <cuda_runtime.h>
#include <cuda_fp16.h>
#include <cstdint>
#include <math.h>

#define SS 2048
#define DD 1024
#define HH 8

// ---------------- scratch (__device__ globals; allocation-free rule) -------
__device__ __half g_hid_hi[SS * DD];
__device__ __half g_hid_lo[SS * DD];
__device__ __half g_w2t_hi[DD * DD];
__device__ __half g_w2t_lo[DD * DD];
__device__ __half g_awt_hi[HH * DD * DD];
__device__ __half g_awt_lo[HH * DD * DD];
__device__ __half g_x_hi[SS * DD];
__device__ __half g_x_lo[SS * DD];
__device__ __half g_xt[DD * SS];
__device__ __half g_owt[DD * HH * DD];
__device__ __half g_rel_hi[SS * DD];
__device__ __half g_rel_lo[SS * DD];
__device__ __half g_Q_hi[HH * SS * DD];
__device__ __half g_Q_lo[HH * SS * DD];
__device__ float  g_logits[(size_t)HH * SS * SS];
__device__ __half g_probs[(size_t)HH * SS * SS];
__device__ __half g_ctx[(size_t)SS * HH * DD];

// ---------------- helpers ---------------------------------------------------
__device__ __forceinline__ uint32_t smem_u32(const void* p) {
    uint32_t a;
    asm("{ .reg .u64 t; cvta.to.shared.u64 t, %1; cvt.u32.u64 %0, t; }"
        : "=r"(a) : "l"(p));
    return a;
}
// k-permutation (within 32-groups) for fp16 m16n8k16 fragments.
// inverse: natural k stored at position p
__device__ __forceinline__ int invp(int p) {            // p in [0,32)
    return (p & 1) | (((p >> 3) & 3) << 1) | (((p >> 1) & 1) << 3) |
           (((p >> 2) & 1) << 4);
}
__device__ __forceinline__ uint32_t pack2(float x, float y) {
    __half hx = __float2half_rn(x), hy = __float2half_rn(y);
    return (uint32_t)__half_as_ushort(hx) |
           ((uint32_t)__half_as_ushort(hy) << 16);
}
__device__ __forceinline__ float lo_of(float v) {
    return v - __half2float(__float2half_rn(v));
}
__device__ __forceinline__ void mma16(float* d, uint32_t a0, uint32_t a1,
                                      uint32_t a2, uint32_t a3, uint32_t b0,
                                      uint32_t b1) {
    asm volatile(
        "mma.sync.aligned.m16n8k16.row.col.f32.f16.f16.f32 "
        "{%0,%1,%2,%3},{%4,%5,%6,%7},{%8,%9},{%0,%1,%2,%3};"
        : "+f"(d[0]), "+f"(d[1]), "+f"(d[2]), "+f"(d[3])
        : "r"(a0), "r"(a1), "r"(a2), "r"(a3), "r"(b0), "r"(b1));
}

#define TBYTES 16384          // one 128-row x 64-k half tile
#define TU32 4096             // same tile in uint32s
#define SROW 132              // fp32 staging row stride (floats)
#define NSTG 3                // pipeline stages

// async-copy one 128x64-half tile (128B/row); gmem k-pre-permuted; XOR swizzle
__device__ __forceinline__ void tile_async_h(uint32_t sdst, const __half* src,
                                             int ldh, int kc, int tid) {
#pragma unroll
    for (int t = 0; t < 4; t++) {
        int idx = tid + t * 256;          // 0..1023 16B chunks
        int r = idx >> 3, j = idx & 7;
        uint32_t dst = sdst + (uint32_t)(((r << 3) + (j ^ (r & 7))) << 4);
        const __half* s = src + (size_t)r * ldh + kc + j * 8;
        asm volatile("cp.async.cg.shared.global [%0], [%1], 16;" ::"r"(dst),
                     "l"(s));
    }
}

// fragment read: 16B = the 8 operand halves a lane needs for 2 k16-mmas
__device__ __forceinline__ uint4 fragh(const uint32_t* tile, int r, int j) {
    return *(const uint4*)(tile + r * 32 + ((j ^ (r & 7)) << 2));
}

// plain pass: one (A x B) over a 64-k chunk
__device__ __forceinline__ void pass_h(const uint32_t* As, const uint32_t* Bs,
                                       float acc[4][4][4], int wm, int wn,
                                       int g, int c) {
#pragma unroll
    for (int sp = 0; sp < 2; sp++) {
        int j = sp * 4 + c;
        uint4 a0[4], a1[4], bb[4];
#pragma unroll
        for (int mt = 0; mt < 4; mt++) {
            int r0 = wm + mt * 16 + g;
            a0[mt] = fragh(As, r0, j);
            a1[mt] = fragh(As, r0 + 8, j);
        }
#pragma unroll
        for (int nt = 0; nt < 4; nt++) bb[nt] = fragh(Bs, wn + nt * 8 + g, j);
#pragma unroll
        for (int kk = 0; kk < 2; kk++)
#pragma unroll
            for (int mt = 0; mt < 4; mt++) {
                uint32_t A0 = kk ? a0[mt].z : a0[mt].x;
                uint32_t A2 = kk ? a0[mt].w : a0[mt].y;
                uint32_t A1 = kk ? a1[mt].z : a1[mt].x;
                uint32_t A3 = kk ? a1[mt].w : a1[mt].y;
#pragma unroll
                for (int nt = 0; nt < 4; nt++) {
                    uint32_t B0 = kk ? bb[nt].z : bb[nt].x;
                    uint32_t B1 = kk ? bb[nt].w : bb[nt].y;
                    mma16(acc[mt][nt], A0, A1, A2, A3, B0, B1);
                }
            }
    }
}

// split pass with fragment reuse: loads hi+lo frags once, 3 MMA products
__device__ __forceinline__ void pass_split_h(
    const uint32_t* Ah, const uint32_t* Bh, const uint32_t* Al,
    const uint32_t* Bl, float acc[4][4][4], int wm, int wn, int g, int c) {
#pragma unroll
    for (int sp = 0; sp < 2; sp++) {
        int j = sp * 4 + c;
        uint4 ah0[4], ah1[4], al0[4], al1[4], bh[4], bl[4];
#pragma unroll
        for (int mt = 0; mt < 4; mt++) {
            int r0 = wm + mt * 16 + g;
            ah0[mt] = fragh(Ah, r0, j);
            ah1[mt] = fragh(Ah, r0 + 8, j);
            al0[mt] = fragh(Al, r0, j);
            al1[mt] = fragh(Al, r0 + 8, j);
        }
#pragma unroll
        for (int nt = 0; nt < 4; nt++) {
            int n = wn + nt * 8 + g;
            bh[nt] = fragh(Bh, n, j);
            bl[nt] = fragh(Bl, n, j);
        }
#pragma unroll
        for (int kk = 0; kk < 2; kk++)
#pragma unroll
            for (int mt = 0; mt < 4; mt++) {
                uint32_t H0 = kk ? ah0[mt].z : ah0[mt].x;
                uint32_t H2 = kk ? ah0[mt].w : ah0[mt].y;
                uint32_t H1 = kk ? ah1[mt].z : ah1[mt].x;
                uint32_t H3 = kk ? ah1[mt].w : ah1[mt].y;
                uint32_t L0 = kk ? al0[mt].z : al0[mt].x;
                uint32_t L2 = kk ? al0[mt].w : al0[mt].y;
                uint32_t L1 = kk ? al1[mt].z : al1[mt].x;
                uint32_t L3 = kk ? al1[mt].w : al1[mt].y;
#pragma unroll
                for (int nt = 0; nt < 4; nt++) {
                    uint32_t BH0 = kk ? bh[nt].z : bh[nt].x;
                    uint32_t BH1 = kk ? bh[nt].w : bh[nt].y;
                    uint32_t BL0 = kk ? bl[nt].z : bl[nt].x;
                    uint32_t BL1 = kk ? bl[nt].w : bl[nt].y;
                    mma16(acc[mt][nt], H0, H1, H2, H3, BH0, BH1);
                    mma16(acc[mt][nt], H0, H1, H2, H3, BL0, BL1);
                    mma16(acc[mt][nt], L0, L1, L2, L3, BH0, BH1);
                }
            }
    }
}

// ---------------------------------------------------------------------------
// fp16 m16n8k16 NT GEMM with 3-stage cp.async ring (prefetch distance 2).
// C[M,N] = A[M,K] @ B[N,K]^T (+bias). Operand k-dims gmem-pre-permuted.
// SPLIT: 3-product hi/lo limbs. outHalf: half output, column k-permuted.
// perm != 0: output row r -> (r&7)*SS + z*256 + (r>>3)   (torch .view fold)
// ---------------------------------------------------------------------------
template <bool SPLIT>
__global__ void __launch_bounds__(256, SPLIT ? 1 : 2)
hgemm(const __half* __restrict__ A0, const __half* __restrict__ A1,
      const __half* __restrict__ B0, const __half* __restrict__ B1,
      const float* __restrict__ bias, void* Cv, void* Clov,
      int M, int N, int K, int lda, int ldb, int ldc,
      long aZ, long bZ, long cZ, int perm, int outHalf) {
    extern __shared__ float smf[];
    uint32_t* smu = (uint32_t*)smf;
    const int NT = SPLIT ? 4 : 2;
    const uint32_t sb = smem_u32(smf);

    const int tid = threadIdx.x;
    const int warp = tid >> 5, lane = tid & 31;
    const int g = lane >> 2, c = lane & 3;
    const int m0 = blockIdx.y * 128, n0 = blockIdx.x * 128;
    const int z = blockIdx.z;
    const int wm = (warp >> 2) * 64;
    const int wn = (warp & 3) * 32;

    const __half* Ag = A0 + (size_t)z * aZ + (size_t)m0 * lda;
    const __half* Bg = B0 + (size_t)z * bZ + (size_t)n0 * ldb;
    const __half* Ag1 = SPLIT ? A1 + (size_t)z * aZ + (size_t)m0 * lda : nullptr;
    const __half* Bg1 = SPLIT ? B1 + (size_t)z * bZ + (size_t)n0 * ldb : nullptr;

    float acc[4][4][4];
#pragma unroll
    for (int i = 0; i < 4; i++)
#pragma unroll
        for (int j = 0; j < 4; j++)
#pragma unroll
            for (int k = 0; k < 4; k++) acc[i][j][k] = 0.0f;

    const int nchunks = K >> 6;

    // prologue: prefetch chunks 0 and 1
#pragma unroll
    for (int s = 0; s < 2; s++) {
        if (s < nchunks) {
            uint32_t bs = sb + (uint32_t)(s * NT * TBYTES);
            tile_async_h(bs, Ag, lda, s * 64, tid);
            tile_async_h(bs + TBYTES, Bg, ldb, s * 64, tid);
            if (SPLIT) {
                tile_async_h(bs + 2 * TBYTES, Ag1, lda, s * 64, tid);
                tile_async_h(bs + 3 * TBYTES, Bg1, ldb, s * 64, tid);
            }
            asm volatile("cp.async.commit_group;");
        }
    }

    int bufc = 0, buff = 2 % NSTG;
    for (int i = 0; i < nchunks; i++) {
        __syncthreads();    // all warps done with chunk i-1 (frees ring slot)
        int nf = i + 2;
        if (nf < nchunks) {
            uint32_t bs = sb + (uint32_t)(buff * NT * TBYTES);
            tile_async_h(bs, Ag, lda, nf * 64, tid);
            tile_async_h(bs + TBYTES, Bg, ldb, nf * 64, tid);
            if (SPLIT) {
                tile_async_h(bs + 2 * TBYTES, Ag1, lda, nf * 64, tid);
                tile_async_h(bs + 3 * TBYTES, Bg1, ldb, nf * 64, tid);
            }
            asm volatile("cp.async.commit_group;");
            asm volatile("cp.async.wait_group 2;");
        } else if (i + 1 < nchunks) {
            asm volatile("cp.async.wait_group 1;");
        } else {
            asm volatile("cp.async.wait_group 0;");
        }
        __syncthreads();    // chunk i visible to all warps

        const uint32_t* Ah = smu + bufc * NT * TU32;
        const uint32_t* Bh = Ah + TU32;
        if (SPLIT)
            pass_split_h(Ah, Bh, Ah + 2 * TU32, Ah + 3 * TU32, acc, wm, wn, g, c);
        else
            pass_h(Ah, Bh, acc, wm, wn, g, c);

        bufc = (bufc + 1) % NSTG;
        buff = (buff + 1) % NSTG;
    }

    // ---- staged epilogue: stage fp32 once per half-tile, flush coalesced ---
    float* stage = smf;
#pragma unroll 1
    for (int h128 = 0; h128 < 2; h128++) {
        __syncthreads();
        if ((warp >> 2) == h128) {
#pragma unroll
            for (int mt = 0; mt < 4; mt++)
#pragma unroll
                for (int hf = 0; hf < 2; hf++) {
                    int lrow = mt * 16 + g + hf * 8;
#pragma unroll
                    for (int nt = 0; nt < 4; nt++) {
                        int col = wn + nt * 8 + c * 2;
                        float v0 = acc[mt][nt][hf * 2 + 0];
                        float v1 = acc[mt][nt][hf * 2 + 1];
                        if (bias) {
                            v0 += bias[n0 + col];
                            v1 += bias[n0 + col + 1];
                        }
                        stage[lrow * SROW + col] = v0;
                        stage[lrow * SROW + col + 1] = v1;
                    }
                }
        }
        __syncthreads();

        if (outHalf) {
            __half* Cb = (__half*)Cv + (size_t)z * cZ;
            __half* Lb = Clov ? (__half*)Clov + (size_t)z * cZ : nullptr;
            const int nR = Lb ? 2 : 1;
#pragma unroll 1
            for (int rnd = 0; rnd < nR; rnd++) {
                __half* Ob = rnd ? Lb : Cb;
#pragma unroll
                for (int i = 0; i < 4; i++) {
                    int flat = tid + i * 256;
                    int jg = flat & 15, lrow = flat >> 4;
                    int row = m0 + h128 * 64 + lrow;
                    long crow = perm ? ((long)(row & 7) * SS + (long)z * 256 +
                                        (row >> 3))
                                     : (long)row;
                    int p0 = jg * 8;
                    int cc = (p0 >> 3) & 3, base = p0 & ~31;
                    const float* sr = stage + lrow * SROW + base + 2 * cc;
                    float f[8];
                    f[0] = sr[0];  f[1] = sr[1];
                    f[2] = sr[8];  f[3] = sr[9];
                    f[4] = sr[16]; f[5] = sr[17];
                    f[6] = sr[24]; f[7] = sr[25];
                    if (rnd) {
#pragma unroll
                        for (int e = 0; e < 8; e++) f[e] = lo_of(f[e]);
                    }
                    uint4 o;
                    o.x = pack2(f[0], f[1]);
                    o.y = pack2(f[2], f[3]);
                    o.z = pack2(f[4], f[5]);
                    o.w = pack2(f[6], f[7]);
                    *(uint4*)&Ob[crow * (long)ldc + n0 + p0] = o;
                }
            }
        } else {
            float* Ob = (float*)Cv + (size_t)z * cZ;
#pragma unroll
            for (int i = 0; i < 8; i++) {
                int flat = tid + i * 256;
                int jg = flat & 31, lrow = flat >> 5;
                int row = m0 + h128 * 64 + lrow;
                long crow = perm ? ((long)(row & 7) * SS + (long)z * 256 +
                                    (row >> 3))
                                 : (long)row;
                float4 v = *(const float4*)&stage[lrow * SROW + jg * 4];
                *(float4*)&Ob[crow * (long)ldc + n0 + jg * 4] = v;
            }
        }
    }
}

// ---------------- prep kernels ----------------------------------------------
__global__ void relenc1_split(const float* __restrict__ rel4,
                              const float* __restrict__ w1,
                              const float* __restrict__ b1,
                              __half* __restrict__ hi, __half* __restrict__ lo) {
    int idx = blockIdx.x * 256 + threadIdx.x;
    int s = idx >> 10, p = idx & 1023;
    int j = (p & ~31) | invp(p & 31);
    float acc = b1[j];
#pragma unroll
    for (int k = 0; k < 4; k++) acc = fmaf(rel4[s * 4 + k], w1[k * 1024 + j], acc);
    acc = fmaxf(acc, 0.0f);
    __half h = __float2half_rn(acc);
    hi[idx] = h;
    lo[idx] = __float2half_rn(acc - __half2float(h));
}

// fused transpose for re_w2 (z=0) + attn_w (z=1..8): out[c][perm(r)] half pair
__global__ void transpose_wqa(const float* __restrict__ w2,
                              const float* __restrict__ aw,
                              __half* __restrict__ w2hi, __half* __restrict__ w2lo,
                              __half* __restrict__ awhi, __half* __restrict__ awlo) {
    __shared__ float t[32][33];
    int z = blockIdx.z;
    const float* in = (z == 0) ? w2 : aw + (size_t)(z - 1) * DD * DD;
    __half* ohi = (z == 0) ? w2hi : awhi + (size_t)(z - 1) * DD * DD;
    __half* olo = (z == 0) ? w2lo : awlo + (size_t)(z - 1) * DD * DD;
    int r0 = blockIdx.y * 32, c0 = blockIdx.x * 32;
#pragma unroll
    for (int i = 0; i < 32; i += 8)
        t[threadIdx.y + i][threadIdx.x] =
            in[(size_t)(r0 + threadIdx.y + i) * DD + c0 + threadIdx.x];
    __syncthreads();
    int tx = threadIdx.x, sx = invp(tx);
#pragma unroll
    for (int i = 0; i < 32; i += 8) {
        float v = t[sx][threadIdx.y + i];
        size_t o = (size_t)(c0 + threadIdx.y + i) * DD + r0 + tx;
        __half h = __float2half_rn(v);
        ohi[o] = h;
        olo[o] = __float2half_rn(v - __half2float(h));
    }
}

// fused x prep: x_hi/lo [S][perm D]  AND  xt [D][perm S]
__global__ void prep_x(const float* __restrict__ x, __half* __restrict__ xhi,
                       __half* __restrict__ xlo, __half* __restrict__ xt) {
    __shared__ float t[32][33];
    int r0 = blockIdx.y * 32, c0 = blockIdx.x * 32;   // r over S, c over D
#pragma unroll
    for (int i = 0; i < 32; i += 8)
        t[threadIdx.y + i][threadIdx.x] =
            x[(size_t)(r0 + threadIdx.y + i) * DD + c0 + threadIdx.x];
    __syncthreads();
    int tx = threadIdx.x, sx = invp(tx);
#pragma unroll
    for (int i = 0; i < 32; i += 8) {
        float v = t[threadIdx.y + i][sx];
        size_t o = (size_t)(r0 + threadIdx.y + i) * DD + c0 + tx;
        __half h = __float2half_rn(v);
        xhi[o] = h;
        xlo[o] = __float2half_rn(v - __half2float(h));
        float u = t[sx][threadIdx.y + i];
        xt[(size_t)(c0 + threadIdx.y + i) * SS + r0 + tx] = __float2half_rn(u);
    }
}

// out_w [8192,1024] -> owt [1024][perm 8192], single limb
__global__ void transpose_owt(const float* __restrict__ in,
                              __half* __restrict__ ot) {
    __shared__ float t[32][33];
    int r0 = blockIdx.y * 32, c0 = blockIdx.x * 32;
#pragma unroll
    for (int i = 0; i < 32; i += 8)
        t[threadIdx.y + i][threadIdx.x] =
            in[(size_t)(r0 + threadIdx.y + i) * DD + c0 + threadIdx.x];
    __syncthreads();
    int tx = threadIdx.x, sx = invp(tx);
#pragma unroll
    for (int i = 0; i < 32; i += 8)
        ot[(size_t)(c0 + threadIdx.y + i) * (HH * DD) + r0 + tx] =
            __float2half_rn(t[sx][threadIdx.y + i]);
}

// ---------------- softmax: fp32 logits -> half probs (k-permuted) -----------
__global__ void softmax_kernel(const float* __restrict__ L,
                               __half* __restrict__ P) {
    const float* p = L + (size_t)blockIdx.x * SS;
    __half* q = P + (size_t)blockIdx.x * SS;
    const int tid = threadIdx.x;
    __shared__ float red[8];
    __shared__ float sbuf[SS];

    float4 v[2];
    v[0] = *(const float4*)&p[tid * 4];
    v[1] = *(const float4*)&p[1024 + tid * 4];

    float m = fmaxf(fmaxf(fmaxf(v[0].x, v[0].y), fmaxf(v[0].z, v[0].w)),
                    fmaxf(fmaxf(v[1].x, v[1].y), fmaxf(v[1].z, v[1].w)));
#pragma unroll
    for (int s = 16; s > 0; s >>= 1)
        m = fmaxf(m, __shfl_xor_sync(0xFFFFFFFF, m, s));
    if ((tid & 31) == 0) red[tid >> 5] = m;
    __syncthreads();
    m = fmaxf(fmaxf(fmaxf(red[0], red[1]), fmaxf(red[2], red[3])),
              fmaxf(fmaxf(red[4], red[5]), fmaxf(red[6], red[7])));
    __syncthreads();

    float sum = 0.0f;
#pragma unroll
    for (int h = 0; h < 2; h++) {
        float* f = (float*)&v[h];
#pragma unroll
        for (int e = 0; e < 4; e++) {
            f[e] = __expf(f[e] - m);
            sum += f[e];
        }
    }
#pragma unroll
    for (int s = 16; s > 0; s >>= 1) sum += __shfl_xor_sync(0xFFFFFFFF, sum, s);
    if ((tid & 31) == 0) red[tid >> 5] = sum;
    __syncthreads();
    sum = red[0] + red[1] + red[2] + red[3] + red[4] + red[5] + red[6] + red[7];
    float inv = 1.0f / sum;

#pragma unroll
    for (int h = 0; h < 2; h++) {
        float* f = (float*)&v[h];
#pragma unroll
        for (int e = 0; e < 4; e++)
            sbuf[h * 1024 + tid * 4 + e] = f[e] * inv;
    }
    __syncthreads();

    {
        int p0 = tid * 8;
        int cc = (p0 >> 3) & 3, base = p0 & ~31;
        const float* sr = sbuf + base + 2 * cc;
        uint4 o;
        o.x = pack2(sr[0], sr[1]);
        o.y = pack2(sr[8], sr[9]);
        o.z = pack2(sr[16], sr[17]);
        o.w = pack2(sr[24], sr[25]);
        *(uint4*)&q[p0] = o;
    }
}

// ---------------------------------------------------------------------------
extern "C" void kernel_launch(void* const* d_in, const int* in_sizes, int n_in,
                              void* d_out, int out_size) {
    const float* x         = (const float*)d_in[0];
    const float* relations = (const float*)d_in[1];
    const float* re_w1     = (const float*)d_in[2];
    const float* re_b1     = (const float*)d_in[3];
    const float* re_w2     = (const float*)d_in[4];
    const float* re_b2     = (const float*)d_in[5];
    const float* attn_w    = (const float*)d_in[6];
    const float* out_w     = (const float*)d_in[7];
    const float* out_b     = (const float*)d_in[8];
    float* out = (float*)d_out;

    __half *hid_hi, *hid_lo, *w2t_hi, *w2t_lo, *awt_hi, *awt_lo;
    __half *x_hi, *x_lo, *xt, *owt, *rel_hi, *rel_lo, *Q_hi, *Q_lo, *probs, *ctx;
    float* Lg;
    cudaGetSymbolAddress((void**)&hid_hi, g_hid_hi);
    cudaGetSymbolAddress((void**)&hid_lo, g_hid_lo);
    cudaGetSymbolAddress((void**)&w2t_hi, g_w2t_hi);
    cudaGetSymbolAddress((void**)&w2t_lo, g_w2t_lo);
    cudaGetSymbolAddress((void**)&awt_hi, g_awt_hi);
    cudaGetSymbolAddress((void**)&awt_lo, g_awt_lo);
    cudaGetSymbolAddress((void**)&x_hi, g_x_hi);
    cudaGetSymbolAddress((void**)&x_lo, g_x_lo);
    cudaGetSymbolAddress((void**)&xt, g_xt);
    cudaGetSymbolAddress((void**)&owt, g_owt);
    cudaGetSymbolAddress((void**)&rel_hi, g_rel_hi);
    cudaGetSymbolAddress((void**)&rel_lo, g_rel_lo);
    cudaGetSymbolAddress((void**)&Q_hi, g_Q_hi);
    cudaGetSymbolAddress((void**)&Q_lo, g_Q_lo);
    cudaGetSymbolAddress((void**)&Lg, g_logits);
    cudaGetSymbolAddress((void**)&probs, g_probs);
    cudaGetSymbolAddress((void**)&ctx, g_ctx);

    const int SM_SPLIT = NSTG * 4 * TBYTES;   // 196608 B, 1 CTA/SM
    const int SM_PLAIN = NSTG * 2 * TBYTES;   // 98304 B, 2 CTAs/SM
    cudaFuncSetAttribute(hgemm<true>, cudaFuncAttributeMaxDynamicSharedMemorySize,
                         SM_SPLIT);
    cudaFuncSetAttribute(hgemm<false>, cudaFuncAttributeMaxDynamicSharedMemorySize,
                         SM_PLAIN);

    relenc1_split<<<(SS * DD) / 256, 256>>>(relations, re_w1, re_b1, hid_hi,
                                            hid_lo);
    transpose_wqa<<<dim3(32, 32, 9), dim3(32, 8)>>>(re_w2, attn_w, w2t_hi,
                                                    w2t_lo, awt_hi, awt_lo);
    hgemm<true><<<dim3(8, 16, 1), 256, SM_SPLIT>>>(
        hid_hi, hid_lo, w2t_hi, w2t_lo, re_b2, rel_hi, rel_lo,
        SS, DD, DD, DD, DD, DD, 0, 0, 0, 0, 1);
    prep_x<<<dim3(32, 64), dim3(32, 8)>>>(x, x_hi, x_lo, xt);
    hgemm<true><<<dim3(8, 16, 8), 256, SM_SPLIT>>>(
        x_hi, x_lo, awt_hi, awt_lo, nullptr, Q_hi, Q_lo,
        SS, DD, DD, DD, DD, DD, 0, (long)DD * DD, 0, 1, 1);
    hgemm<true><<<dim3(16, 16, 8), 256, SM_SPLIT>>>(
        rel_hi, rel_lo, Q_hi, Q_lo, nullptr, Lg, nullptr,
        SS, SS, DD, DD, DD, SS, 0, (long)SS * DD, (long)SS * SS, 0, 0);
    softmax_kernel<<<HH * SS, 256>>>(Lg, probs);
    hgemm<false><<<dim3(8, 16, 8), 256, SM_PLAIN>>>(
        probs, nullptr, xt, nullptr, nullptr, ctx, nullptr,
        SS, DD, SS, SS, SS, HH * DD, (long)SS * SS, 0, (long)DD, 0, 1);
    transpose_owt<<<dim3(32, 256), dim3(32, 8)>>>(out_w, owt);
    hgemm<false><<<dim3(8, 16, 1), 256, SM_PLAIN>>>(
        ctx, nullptr, owt, nullptr, out_b, out, nullptr,
        SS, DD, HH * DD, HH * DD, HH * DD, DD, 0, 0, 0, 0, 0);
}